// round 9
// baseline (speedup 1.0000x reference)
#include <cuda_runtime.h>
#include <cuda_bf16.h>
#include <cstdint>

#define BATCH 64
#define CH 64
#define HH 112
#define WW 112
#define HWPIX (HH*WW)          // 12544
#define NP 128                 // pixels per tile
#define TPB 7
#define BLKX 14                // 14*7*128 = 12544
#define EPSV 1e-5f

// device scratch (no cudaMalloc allowed)
__device__ float g_context[BATCH*CH*CH];   // [b][c][d]
__device__ float g_dynw[BATCH*CH*9];       // [b*c][9]

// ---------------- smem layout (bytes) ----------------
// X  : [64 ch][136 stride] bf16 (hi,lo), SINGLE buffer
// W  : [128 out][72 stride] bf16 (hi,lo)
// KV : [128 px][136 stride] bf16 (hi,lo), DOUBLE buffered
#define XSTR  136
#define WSTR  72
#define KVSTR 136
#define OFF_XHI  0             // lo at +17408
#define OFF_WHI  34816         // lo at +18432
#define OFF_WLO  53248
#define OFF_KV0  71680         // hi; lo at +34816
#define OFF_KV1  141312        // hi; lo at +34816
#define KVLO     34816
#define SMEMB    210944

// ---------------- helpers ----------------
__device__ __forceinline__ uint32_t smem_u32(const void* p){
  uint32_t a;
  asm("{ .reg .u64 t; cvta.to.shared.u64 t, %1; cvt.u32.u64 %0, t; }" : "=r"(a) : "l"(p));
  return a;
}
__device__ __forceinline__ void ldsm4(uint32_t* r, uint32_t addr){
  asm volatile("ldmatrix.sync.aligned.m8n8.x4.shared.b16 {%0,%1,%2,%3}, [%4];"
    : "=r"(r[0]), "=r"(r[1]), "=r"(r[2]), "=r"(r[3]) : "r"(addr));
}
__device__ __forceinline__ void ldsm4t(uint32_t* r, uint32_t addr){
  asm volatile("ldmatrix.sync.aligned.m8n8.x4.trans.shared.b16 {%0,%1,%2,%3}, [%4];"
    : "=r"(r[0]), "=r"(r[1]), "=r"(r[2]), "=r"(r[3]) : "r"(addr));
}
__device__ __forceinline__ void mma16816(float* d, const uint32_t* a, uint32_t b0, uint32_t b1){
  asm volatile("mma.sync.aligned.m16n8k16.row.col.f32.bf16.bf16.f32 "
    "{%0,%1,%2,%3}, {%4,%5,%6,%7}, {%8,%9}, {%0,%1,%2,%3};"
    : "+f"(d[0]), "+f"(d[1]), "+f"(d[2]), "+f"(d[3])
    : "r"(a[0]), "r"(a[1]), "r"(a[2]), "r"(a[3]), "r"(b0), "r"(b1));
}
// truncation split: hi = bits & 0xffff0000 (exact bf16), lo = rn_bf16(f - hi)
__device__ __forceinline__ void split_store(uint32_t* ph, uint32_t* pl, int bi,
                                            float f0, float f1){
  uint32_t u0 = __float_as_uint(f0), u1 = __float_as_uint(f1);
  ph[bi] = __byte_perm(u0, u1, 0x7632);                 // [hi16(u0), hi16(u1)]
  float h0 = __uint_as_float(u0 & 0xffff0000u);
  float h1 = __uint_as_float(u1 & 0xffff0000u);
  __nv_bfloat162 t = __floats2bfloat162_rn(f0 - h0, f1 - h1);
  pl[bi] = *(uint32_t*)&t;
}

__global__ void __launch_bounds__(256) zero_ctx_kernel(){
  int i = blockIdx.x * blockDim.x + threadIdx.x;   // 65536 float4
  ((float4*)g_context)[i] = make_float4(0.f,0.f,0.f,0.f);
}

// ============ fused attention: bf16x3 HMMA, MMA-before-scalar pipeline ============
__global__ void __launch_bounds__(256, 1) attn_ctx_mma(
    const float* __restrict__ x,
    const float* __restrict__ Wv, const float* __restrict__ bvp,
    const float* __restrict__ Wm, const float* __restrict__ bm,
    const float* __restrict__ gma, const float* __restrict__ bta,
    const float* __restrict__ mu,  const float* __restrict__ var)
{
  extern __shared__ char smc[];
  const uint32_t sb = smem_u32(smc);
  const int tid = threadIdx.x;
  const int w   = tid >> 5;        // warp 0..7
  const int l   = tid & 31;
  const int b   = blockIdx.y;

  const int lk = (l & 7) + 8 * (l >> 4);     // ldmatrix row term
  const int lc = 8 * ((l >> 3) & 1);         // ldmatrix col term
  const int cl2 = 2 * (l & 3);

  const float* xb = x + (size_t)b * CH * HWPIX;

  // ---- prefetch X tile 0 into registers ----
  float4 xr[8];
  {
    const int n0 = blockIdx.x * TPB * NP;
    #pragma unroll
    for (int i = 0; i < 8; i++) {
      int f4 = tid + 256 * i;
      int chn = f4 >> 5, pxf = f4 & 31;
      xr[i] = __ldg((const float4*)(xb + (size_t)chn * HWPIX + n0) + pxf);
    }
  }

  // ---- load W (rows 0-63 = Wv, 64-127 = Wm*bnscale), bf16 hi/lo, once ----
  {
    uint32_t* ph = (uint32_t*)(smc + OFF_WHI);
    uint32_t* pl = (uint32_t*)(smc + OFF_WLO);
    #pragma unroll
    for (int i = 0; i < 8; i++) {
      int f4 = tid + 256 * i;        // 2048 float4
      int o  = f4 >> 4;
      int c4 = (f4 & 15) * 4;
      float4 v;
      float s = 1.f;
      if (o < 64) v = __ldg((const float4*)(Wv + o*64 + c4));
      else {
        int oo = o - 64;
        v = __ldg((const float4*)(Wm + oo*64 + c4));
        s = __ldg(gma + oo) * rsqrtf(__ldg(var + oo) + EPSV);
      }
      v.x *= s; v.y *= s; v.z *= s; v.w *= s;
      int bi = o * (WSTR/2) + (c4 >> 1);
      split_store(ph, pl, bi,     v.x, v.y);
      split_store(ph, pl, bi + 1, v.z, v.w);
    }
  }

  // ---- per-thread constants: BN shift for K cols, bias for V cols ----
  float kshr[16], bvr[16];
  #pragma unroll
  for (int nt = 0; nt < 8; nt++)
    #pragma unroll
    for (int j = 0; j < 2; j++) {
      int col = nt*8 + cl2 + j;
      bvr[2*nt + j] = __ldg(bvp + col);
      float sc = __ldg(gma + col) * rsqrtf(__ldg(var + col) + EPSV);
      kshr[2*nt + j] = (__ldg(bm + col) - __ldg(mu + col)) * sc + __ldg(bta + col);
    }

  // ---- convert X(0) into Xsm ----
  auto conv_x = [&](){
    uint32_t* ph = (uint32_t*)(smc + OFF_XHI);
    uint32_t* pl = (uint32_t*)(smc + OFF_XHI + 17408);
    #pragma unroll
    for (int i = 0; i < 8; i++) {
      int f4  = tid + 256 * i;
      int chn = f4 >> 5, pxf = f4 & 31;
      int bi = chn * (XSTR/2) + pxf * 2;
      split_store(ph, pl, bi,     xr[i].x, xr[i].y);
      split_store(ph, pl, bi + 1, xr[i].z, xr[i].w);
    }
  };
  conv_x();

  // ---- stage-2 persistent accumulators ----
  const int c_base = (w >> 1) * 16;
  const int d_base = (w & 1) * 32;
  float acc2[4][4];
  #pragma unroll
  for (int i = 0; i < 4; i++)
    #pragma unroll
    for (int j = 0; j < 4; j++) acc2[i][j] = 0.f;

  // ldmatrix base byte offsets
  const uint32_t a1off  = sb + OFF_XHI + (uint32_t)(lk*XSTR + 16*w + lc) * 2;
  const uint32_t b1off  = sb + OFF_WHI + (uint32_t)(lk*WSTR + lc) * 2;
  const uint32_t a2term = (uint32_t)(lk*KVSTR + 64 + c_base + lc) * 2;
  const uint32_t b2term = (uint32_t)(lk*KVSTR + d_base + lc) * 2;

  // stage-2 over one KV buffer
  auto do_stage2 = [&](uint32_t kvbase){
    const uint32_t a2off = kvbase + a2term;
    const uint32_t b2off = kvbase + b2term;
    #pragma unroll
    for (int ks = 0; ks < 8; ks++) {
      uint32_t step = (uint32_t)(ks * 16 * KVSTR) * 2;
      uint32_t ah[4], al[4];
      ldsm4t(ah, a2off + step);
      ldsm4t(al, a2off + step + KVLO);
      #pragma unroll
      for (int dbi = 0; dbi < 2; dbi++) {
        uint32_t bh[4], bl[4];
        uint32_t bo = step + (uint32_t)(dbi * 16) * 2;
        ldsm4t(bh, b2off + bo);
        ldsm4t(bl, b2off + bo + KVLO);
        mma16816(acc2[2*dbi],   ah, bh[0], bh[2]);
        mma16816(acc2[2*dbi],   ah, bl[0], bl[2]);
        mma16816(acc2[2*dbi],   al, bh[0], bh[2]);
        mma16816(acc2[2*dbi+1], ah, bh[1], bh[3]);
        mma16816(acc2[2*dbi+1], ah, bl[1], bl[3]);
        mma16816(acc2[2*dbi+1], al, bh[1], bh[3]);
      }
    }
  };

  __syncthreads();   // W + X(0) visible

  for (int t = 0; t < TPB; t++) {
    // ================= MMA-A: prefetch X(t+1) + stage1(t) =================
    if (t + 1 < TPB) {
      const int n1 = (blockIdx.x * TPB + t + 1) * NP;
      #pragma unroll
      for (int i = 0; i < 8; i++) {
        int f4 = tid + 256 * i;
        int chn = f4 >> 5, pxf = f4 & 31;
        xr[i] = __ldg((const float4*)(xb + (size_t)chn * HWPIX + n1) + pxf);
      }
    }

    float acc1[16][4];
    #pragma unroll
    for (int i = 0; i < 16; i++)
      #pragma unroll
      for (int j = 0; j < 4; j++) acc1[i][j] = 0.f;

    #pragma unroll
    for (int ks = 0; ks < 4; ks++) {
      uint32_t ah[4], al[4];
      uint32_t astep = (uint32_t)(ks * 16 * XSTR) * 2;
      ldsm4t(ah, a1off + astep);
      ldsm4t(al, a1off + astep + 17408u);
      #pragma unroll
      for (int nb = 0; nb < 8; nb++) {
        uint32_t bh[4], bl[4];
        uint32_t bo = (uint32_t)((nb*16) * WSTR + ks*16) * 2;
        ldsm4(bh, b1off + bo);
        ldsm4(bl, b1off + bo + 18432u);
        mma16816(acc1[2*nb],   ah, bh[0], bh[1]);
        mma16816(acc1[2*nb],   ah, bl[0], bl[1]);
        mma16816(acc1[2*nb],   al, bh[0], bh[1]);
        mma16816(acc1[2*nb+1], ah, bh[2], bh[3]);
        mma16816(acc1[2*nb+1], ah, bl[2], bl[3]);
        mma16816(acc1[2*nb+1], al, bh[2], bh[3]);
      }
    }

    // ================= scalar-A: softmax (K cols = ntiles 8..15) ==========
    float m0 = -1e30f, m1 = -1e30f;
    #pragma unroll
    for (int nt = 8; nt < 16; nt++)
      #pragma unroll
      for (int j = 0; j < 2; j++) {
        float sh = kshr[(nt-8)*2 + j];
        acc1[nt][j]   += sh;
        acc1[nt][2+j] += sh;
        m0 = fmaxf(m0, acc1[nt][j]);
        m1 = fmaxf(m1, acc1[nt][2+j]);
      }
    m0 = fmaxf(m0, __shfl_xor_sync(0xffffffffu, m0, 1));
    m0 = fmaxf(m0, __shfl_xor_sync(0xffffffffu, m0, 2));
    m1 = fmaxf(m1, __shfl_xor_sync(0xffffffffu, m1, 1));
    m1 = fmaxf(m1, __shfl_xor_sync(0xffffffffu, m1, 2));
    float s0 = 0.f, s1 = 0.f;
    #pragma unroll
    for (int nt = 8; nt < 16; nt++)
      #pragma unroll
      for (int j = 0; j < 2; j++) {
        acc1[nt][j]   = __expf(acc1[nt][j]   - m0); s0 += acc1[nt][j];
        acc1[nt][2+j] = __expf(acc1[nt][2+j] - m1); s1 += acc1[nt][2+j];
      }
    s0 += __shfl_xor_sync(0xffffffffu, s0, 1);
    s0 += __shfl_xor_sync(0xffffffffu, s0, 2);
    s1 += __shfl_xor_sync(0xffffffffu, s1, 1);
    s1 += __shfl_xor_sync(0xffffffffu, s1, 2);
    const float inv0 = 1.f / s0, inv1 = 1.f / s1;

    __syncthreads();   // syncA: all stage1(t) reads of Xsm done; KVbuf[(t-1)&1] readers of prev iter done

    // ================= MMA-B: stage2(t-1) =================================
    if (t > 0) do_stage2(sb + (((t - 1) & 1) ? OFF_KV1 : OFF_KV0));

    // ================= scalar-B: KV-write(t) + X(t+1) convert =============
    {
      const int r0 = 16*w + (l >> 2);
      uint32_t* ph = (uint32_t*)(smc + ((t & 1) ? OFF_KV1 : OFF_KV0));
      uint32_t* pl = (uint32_t*)((char*)ph + KVLO);
      #pragma unroll
      for (int nt = 0; nt < 16; nt++) {
        float f0, f1, f2, f3;
        if (nt < 8) {
          f0 = acc1[nt][0] + bvr[2*nt];     f1 = acc1[nt][1] + bvr[2*nt+1];
          f2 = acc1[nt][2] + bvr[2*nt];     f3 = acc1[nt][3] + bvr[2*nt+1];
        } else {
          f0 = acc1[nt][0] * inv0;          f1 = acc1[nt][1] * inv0;
          f2 = acc1[nt][2] * inv1;          f3 = acc1[nt][3] * inv1;
        }
        int col = nt*8 + cl2;
        int bi0 = r0       * (KVSTR/2) + (col >> 1);
        int bi1 = (r0 + 8) * (KVSTR/2) + (col >> 1);
        split_store(ph, pl, bi0, f0, f1);
        split_store(ph, pl, bi1, f2, f3);
      }
    }
    if (t + 1 < TPB) conv_x();

    __syncthreads();   // syncB: KVbuf[t&1] + Xsm(t+1) visible
  }

  // epilogue: stage2 of last tile (t=6 -> buf 0)
  do_stage2(sb + OFF_KV0);

  // ---- flush context ----
  float* cp = g_context + (size_t)b * CH * CH;
  const int c0 = c_base + (l >> 2);
  #pragma unroll
  for (int nt = 0; nt < 4; nt++)
    #pragma unroll
    for (int j = 0; j < 2; j++) {
      int d = d_base + nt*8 + cl2 + j;
      atomicAdd(cp + c0*CH + d,       acc2[nt][j]);
      atomicAdd(cp + (c0+8)*CH + d,   acc2[nt][2+j]);
    }
}

// dynw[b,i,j] = sum_m sigmoid(context[b,i,m]) * Wfc[i,j,m] + bfc[i,j]
__global__ void __launch_bounds__(128) dynw_kernel(
    const float* __restrict__ Wfc, const float* __restrict__ bfc)
{
  int warp = blockIdx.x * 4 + (threadIdx.x >> 5);   // 0..4095
  int lane = threadIdx.x & 31;
  int i = warp & 63;
  const float* ctx = g_context + (size_t)warp * 64;
  float a0 = 1.f / (1.f + __expf(-ctx[lane]));
  float a1 = 1.f / (1.f + __expf(-ctx[lane + 32]));
  #pragma unroll
  for (int j = 0; j < 9; j++) {
    float s = a0 * Wfc[(i*9 + j)*64 + lane] + a1 * Wfc[(i*9 + j)*64 + lane + 32];
    #pragma unroll
    for (int o = 16; o > 0; o >>= 1) s += __shfl_xor_sync(0xffffffffu, s, o);
    if (lane == 0) g_dynw[warp*9 + j] = s + bfc[i*9 + j];
  }
}

// depthwise 3x3, pad 1 — float4 per thread, 4 row-groups of 7 rows (round-6 proven)
#define TROWS 28
#define TS_STR 120
__global__ void __launch_bounds__(128) dwconv_kernel(
    const float* __restrict__ x, float* __restrict__ out)
{
  __shared__ float ts[(TROWS + 2) * TS_STR];   // data col s at idx s+4
  const int plane = blockIdx.x;                 // b*64 + c
  const int rb = blockIdx.y * TROWS;
  const float* xp = x + (size_t)plane * HWPIX;
  const int tid = threadIdx.x;

  // float4 fill: 30 rows x 28 float4
  for (int i = tid; i < 840; i += 128) {
    int r = i / 28, k = i - r * 28;
    int gr = rb - 1 + r;
    float4 v = make_float4(0.f, 0.f, 0.f, 0.f);
    if (gr >= 0 && gr < HH) v = __ldg((const float4*)(xp + (size_t)gr * WW) + k);
    *(float4*)&ts[r * TS_STR + 4 + 4*k] = v;
  }
  for (int i = tid; i < 30; i += 128) { ts[i*TS_STR + 3] = 0.f; ts[i*TS_STR + 116] = 0.f; }

  float w[9];
  const float* wp = g_dynw + (size_t)plane * 9;
  #pragma unroll
  for (int k = 0; k < 9; k++) w[k] = __ldg(wp + k);
  __syncthreads();

  if (tid < 112) {
    const int g  = tid / 28;         // row group 0..3 (7 rows each)
    const int c4 = tid - g * 28;     // float4 column 0..27
    const float* rp = ts + (g*7) * TS_STR + 4*c4 + 3;
    float  L0 = rp[0];  float4 F0 = *(const float4*)(rp + 1);  float R0 = rp[5];
    rp += TS_STR;
    float  L1 = rp[0];  float4 F1 = *(const float4*)(rp + 1);  float R1 = rp[5];
    float* op = out + (size_t)plane * HWPIX + (size_t)(rb + g*7) * WW + 4*c4;
    #pragma unroll
    for (int j = 0; j < 7; j++) {
      rp += TS_STR;
      float  L2 = rp[0];  float4 F2 = *(const float4*)(rp + 1);  float R2 = rp[5];
      float4 o;
      o.x = w[0]*L0   + w[1]*F0.x + w[2]*F0.y
          + w[3]*L1   + w[4]*F1.x + w[5]*F1.y
          + w[6]*L2   + w[7]*F2.x + w[8]*F2.y;
      o.y = w[0]*F0.x + w[1]*F0.y + w[2]*F0.z
          + w[3]*F1.x + w[4]*F1.y + w[5]*F1.z
          + w[6]*F2.x + w[7]*F2.y + w[8]*F2.z;
      o.z = w[0]*F0.y + w[1]*F0.z + w[2]*F0.w
          + w[3]*F1.y + w[4]*F1.z + w[5]*F1.w
          + w[6]*F2.y + w[7]*F2.z + w[8]*F2.w;
      o.w = w[0]*F0.z + w[1]*F0.w + w[2]*R0
          + w[3]*F1.z + w[4]*F1.w + w[5]*R1
          + w[6]*F2.z + w[7]*F2.w + w[8]*R2;
      *(float4*)op = o;
      op += WW;
      L0 = L1; F0 = F1; R0 = R1;
      L1 = L2; F1 = F2; R1 = R2;
    }
  }
}

extern "C" void kernel_launch(void* const* d_in, const int* in_sizes, int n_in,
                              void* d_out, int out_size)
{
  const float* x    = (const float*)d_in[0];
  const float* Wv   = (const float*)d_in[1];
  const float* bv   = (const float*)d_in[2];
  const float* Wm   = (const float*)d_in[3];
  const float* bm   = (const float*)d_in[4];
  const float* gma  = (const float*)d_in[5];
  const float* bta  = (const float*)d_in[6];
  const float* mu   = (const float*)d_in[7];
  const float* var  = (const float*)d_in[8];
  const float* Wfc  = (const float*)d_in[9];
  const float* bfc  = (const float*)d_in[10];
  float* out = (float*)d_out;

  cudaFuncSetAttribute(attn_ctx_mma,
                       cudaFuncAttributeMaxDynamicSharedMemorySize, SMEMB);

  zero_ctx_kernel<<<256, 256>>>();
  attn_ctx_mma<<<dim3(BLKX, BATCH), 256, SMEMB>>>(
      x, Wv, bv, Wm, bm, gma, bta, mu, var);
  dynw_kernel<<<1024, 128>>>(Wfc, bfc);
  dwconv_kernel<<<dim3(BATCH * CH, HH / TROWS), 128>>>(x, out);
}

// round 10
// speedup vs baseline: 1.1775x; 1.1775x over previous
#include <cuda_runtime.h>
#include <cuda_bf16.h>
#include <cstdint>

#define BATCH 64
#define CH 64
#define HH 112
#define WW 112
#define HWPIX (HH*WW)          // 12544
#define NP 128                 // pixels per tile
#define TPB 7
#define BLKX 14                // 14*7*128 = 12544
#define EPSV 1e-5f

// device scratch (no cudaMalloc allowed)
__device__ float g_P[BATCH*CH*CH];         // [b][c][e] = sum_p k_c(p) x_e(p)
__device__ float g_kpsum[BATCH*CH];        // [b][c]    = sum_p k_c(p)
__device__ float g_context[BATCH*CH*CH];   // [b][c][d]
__device__ float g_dynw[BATCH*CH*9];       // [b*c][9]

// ---------------- smem layout (bytes) ----------------
// X : [64 ch][136 stride] bf16 (hi,lo), DOUBLE buffered (also stage-2 B operand)
// W : [64 out][72 stride] bf16 (hi,lo)  (Wm * bnscale only)
// K : [128 px][72 stride] bf16 (hi,lo)  (softmaxed key)
#define XSTR  136
#define WSTR  72
#define KSTR  72
#define OFF_XHI0 0             // lo at +17408
#define OFF_XHI1 34816         // lo at +17408
#define XLOD     17408
#define OFF_WHI  69632         // [64][72]*2B = 9216
#define OFF_WLO  78848
#define OFF_KHI  88064         // [128][72]*2B = 18432
#define OFF_KLO  106496
#define OFF_KSH  124928        // 64 floats BN shift
#define SMEMB    125184

// ---------------- helpers ----------------
__device__ __forceinline__ uint32_t smem_u32(const void* p){
  uint32_t a;
  asm("{ .reg .u64 t; cvta.to.shared.u64 t, %1; cvt.u32.u64 %0, t; }" : "=r"(a) : "l"(p));
  return a;
}
__device__ __forceinline__ void ldsm4(uint32_t* r, uint32_t addr){
  asm volatile("ldmatrix.sync.aligned.m8n8.x4.shared.b16 {%0,%1,%2,%3}, [%4];"
    : "=r"(r[0]), "=r"(r[1]), "=r"(r[2]), "=r"(r[3]) : "r"(addr));
}
__device__ __forceinline__ void ldsm4t(uint32_t* r, uint32_t addr){
  asm volatile("ldmatrix.sync.aligned.m8n8.x4.trans.shared.b16 {%0,%1,%2,%3}, [%4];"
    : "=r"(r[0]), "=r"(r[1]), "=r"(r[2]), "=r"(r[3]) : "r"(addr));
}
__device__ __forceinline__ void mma16816(float* d, const uint32_t* a, uint32_t b0, uint32_t b1){
  asm volatile("mma.sync.aligned.m16n8k16.row.col.f32.bf16.bf16.f32 "
    "{%0,%1,%2,%3}, {%4,%5,%6,%7}, {%8,%9}, {%0,%1,%2,%3};"
    : "+f"(d[0]), "+f"(d[1]), "+f"(d[2]), "+f"(d[3])
    : "r"(a[0]), "r"(a[1]), "r"(a[2]), "r"(a[3]), "r"(b0), "r"(b1));
}
// truncation split: hi = bits & 0xffff0000 (exact bf16), lo = rn_bf16(f - hi)
__device__ __forceinline__ void split_store(uint32_t* ph, uint32_t* pl, int bi,
                                            float f0, float f1){
  uint32_t u0 = __float_as_uint(f0), u1 = __float_as_uint(f1);
  ph[bi] = __byte_perm(u0, u1, 0x7632);                 // [hi16(u0), hi16(u1)]
  float h0 = __uint_as_float(u0 & 0xffff0000u);
  float h1 = __uint_as_float(u1 & 0xffff0000u);
  __nv_bfloat162 t = __floats2bfloat162_rn(f0 - h0, f1 - h1);
  pl[bi] = *(uint32_t*)&t;
}

__global__ void __launch_bounds__(256) zero_kernel(){
  int i = blockIdx.x * blockDim.x + threadIdx.x;   // 65536 float4
  ((float4*)g_P)[i] = make_float4(0.f,0.f,0.f,0.f);
  if (i < 1024) ((float4*)g_kpsum)[i] = make_float4(0.f,0.f,0.f,0.f);
}

// ============ fused K-attention: P = softmax(BN(Wm X)) @ X^T, bf16x3 HMMA ============
__global__ void __launch_bounds__(256, 1) attn_p_mma(
    const float* __restrict__ x,
    const float* __restrict__ Wm, const float* __restrict__ bm,
    const float* __restrict__ gma, const float* __restrict__ bta,
    const float* __restrict__ mu,  const float* __restrict__ var)
{
  extern __shared__ char smc[];
  const uint32_t sb = smem_u32(smc);
  const int tid = threadIdx.x;
  const int w   = tid >> 5;        // warp 0..7
  const int l   = tid & 31;
  const int b   = blockIdx.y;

  const int lk = (l & 7) + 8 * (l >> 4);     // ldmatrix row term
  const int lc = 8 * ((l >> 3) & 1);         // ldmatrix col term
  const int cl2 = 2 * (l & 3);

  const float* xb = x + (size_t)b * CH * HWPIX;

  // ---- prefetch X tile 0 into registers ----
  float4 xr[8];
  {
    const int n0 = blockIdx.x * TPB * NP;
    #pragma unroll
    for (int i = 0; i < 8; i++) {
      int f4 = tid + 256 * i;
      int chn = f4 >> 5, pxf = f4 & 31;
      xr[i] = __ldg((const float4*)(xb + (size_t)chn * HWPIX + n0) + pxf);
    }
  }

  // ---- load W = Wm * bnscale (64 rows), bf16 hi/lo, once ----
  {
    uint32_t* ph = (uint32_t*)(smc + OFF_WHI);
    uint32_t* pl = (uint32_t*)(smc + OFF_WLO);
    #pragma unroll
    for (int i = 0; i < 4; i++) {
      int f4 = tid + 256 * i;        // 1024 float4
      int o  = f4 >> 4;
      int c4 = (f4 & 15) * 4;
      float4 v = __ldg((const float4*)(Wm + o*64 + c4));
      float s = __ldg(gma + o) * rsqrtf(__ldg(var + o) + EPSV);
      v.x *= s; v.y *= s; v.z *= s; v.w *= s;
      int bi = o * (WSTR/2) + (c4 >> 1);
      split_store(ph, pl, bi,     v.x, v.y);
      split_store(ph, pl, bi + 1, v.z, v.w);
    }
  }
  // BN shift (folded) into smem
  if (tid < CH) {
    float sc = __ldg(gma + tid) * rsqrtf(__ldg(var + tid) + EPSV);
    *(float*)(smc + OFF_KSH + tid*4) =
        (__ldg(bm + tid) - __ldg(mu + tid)) * sc + __ldg(bta + tid);
  }

  // ---- convert X(0) into buffer 0 ----
  {
    uint32_t* ph = (uint32_t*)(smc + OFF_XHI0);
    uint32_t* pl = (uint32_t*)(smc + OFF_XHI0 + XLOD);
    #pragma unroll
    for (int i = 0; i < 8; i++) {
      int f4  = tid + 256 * i;
      int chn = f4 >> 5, pxf = f4 & 31;
      int bi = chn * (XSTR/2) + pxf * 2;
      split_store(ph, pl, bi,     xr[i].x, xr[i].y);
      split_store(ph, pl, bi + 1, xr[i].z, xr[i].w);
    }
  }

  // ---- persistent accumulators: P tile 16x32 per warp + kpsum partials ----
  const int c_base = (w >> 1) * 16;
  const int d_base = (w & 1) * 32;
  float acc2[4][4];
  #pragma unroll
  for (int i = 0; i < 4; i++)
    #pragma unroll
    for (int j = 0; j < 4; j++) acc2[i][j] = 0.f;
  float ksum[16];
  #pragma unroll
  for (int i = 0; i < 16; i++) ksum[i] = 0.f;

  // ldmatrix base byte offsets
  const uint32_t a1term = (uint32_t)(lk*XSTR + 16*w + lc) * 2;     // + xbuf
  const uint32_t b1off  = sb + OFF_WHI + (uint32_t)(lk*WSTR + lc) * 2;
  const uint32_t a2off  = sb + OFF_KHI + (uint32_t)(lk*KSTR + c_base + lc) * 2;
  const uint32_t b2term = (uint32_t)((d_base + lk)*XSTR + lc) * 2; // + xbuf

  for (int t = 0; t < TPB; t++) {
    const uint32_t xbuf = (t & 1) ? OFF_XHI1 : OFF_XHI0;

    if (t > 0) {
      // convert + store X(t) from regs into buffer t&1
      uint32_t* ph = (uint32_t*)(smc + xbuf);
      uint32_t* pl = (uint32_t*)(smc + xbuf + XLOD);
      #pragma unroll
      for (int i = 0; i < 8; i++) {
        int f4  = tid + 256 * i;
        int chn = f4 >> 5, pxf = f4 & 31;
        int bi = chn * (XSTR/2) + pxf * 2;
        split_store(ph, pl, bi,     xr[i].x, xr[i].y);
        split_store(ph, pl, bi + 1, xr[i].z, xr[i].w);
      }
    }
    __syncthreads();

    // ---- prefetch X(t+1) (hidden behind stage-1 MMAs) ----
    if (t + 1 < TPB) {
      const int n1 = (blockIdx.x * TPB + t + 1) * NP;
      #pragma unroll
      for (int i = 0; i < 8; i++) {
        int f4 = tid + 256 * i;
        int chn = f4 >> 5, pxf = f4 & 31;
        xr[i] = __ldg((const float4*)(xb + (size_t)chn * HWPIX + n1) + pxf);
      }
    }

    // ---- stage 1: logits[16 px of warp][64 ch] = X @ W^T, bf16x3 ----
    float acc1[8][4];
    #pragma unroll
    for (int i = 0; i < 8; i++)
      #pragma unroll
      for (int j = 0; j < 4; j++) acc1[i][j] = 0.f;

    const uint32_t a1off = sb + xbuf + a1term;
    #pragma unroll
    for (int ks = 0; ks < 4; ks++) {
      uint32_t ah[4], al[4];
      uint32_t astep = (uint32_t)(ks * 16 * XSTR) * 2;
      ldsm4t(ah, a1off + astep);
      ldsm4t(al, a1off + astep + XLOD);
      #pragma unroll
      for (int nb = 0; nb < 4; nb++) {
        uint32_t bh[4], bl[4];
        uint32_t bo = (uint32_t)((nb*16) * WSTR + ks*16) * 2;
        ldsm4(bh, b1off + bo);
        ldsm4(bl, b1off + bo + 9216u);
        mma16816(acc1[2*nb],   ah, bh[0], bh[1]);
        mma16816(acc1[2*nb],   ah, bl[0], bl[1]);
        mma16816(acc1[2*nb],   al, bh[0], bh[1]);
        mma16816(acc1[2*nb+1], ah, bh[2], bh[3]);
        mma16816(acc1[2*nb+1], ah, bl[2], bl[3]);
        mma16816(acc1[2*nb+1], al, bh[2], bh[3]);
      }
    }

    // ---- softmax over 64 channels (warp-local, 2 px per thread) ----
    const float* ksm = (const float*)(smc + OFF_KSH);
    float m0 = -1e30f, m1 = -1e30f;
    #pragma unroll
    for (int nt = 0; nt < 8; nt++)
      #pragma unroll
      for (int j = 0; j < 2; j++) {
        float sh = ksm[nt*8 + cl2 + j];
        acc1[nt][j]   += sh;
        acc1[nt][2+j] += sh;
        m0 = fmaxf(m0, acc1[nt][j]);
        m1 = fmaxf(m1, acc1[nt][2+j]);
      }
    m0 = fmaxf(m0, __shfl_xor_sync(0xffffffffu, m0, 1));
    m0 = fmaxf(m0, __shfl_xor_sync(0xffffffffu, m0, 2));
    m1 = fmaxf(m1, __shfl_xor_sync(0xffffffffu, m1, 1));
    m1 = fmaxf(m1, __shfl_xor_sync(0xffffffffu, m1, 2));
    float s0 = 0.f, s1 = 0.f;
    #pragma unroll
    for (int nt = 0; nt < 8; nt++)
      #pragma unroll
      for (int j = 0; j < 2; j++) {
        acc1[nt][j]   = __expf(acc1[nt][j]   - m0); s0 += acc1[nt][j];
        acc1[nt][2+j] = __expf(acc1[nt][2+j] - m1); s1 += acc1[nt][2+j];
      }
    s0 += __shfl_xor_sync(0xffffffffu, s0, 1);
    s0 += __shfl_xor_sync(0xffffffffu, s0, 2);
    s1 += __shfl_xor_sync(0xffffffffu, s1, 1);
    s1 += __shfl_xor_sync(0xffffffffu, s1, 2);
    const float inv0 = 1.f / s0, inv1 = 1.f / s1;

    // ---- write K smem [px][64 ch] bf16 hi/lo + accumulate kpsum ----
    {
      const int r0 = 16*w + (l >> 2);
      uint32_t* ph = (uint32_t*)(smc + OFF_KHI);
      uint32_t* pl = (uint32_t*)(smc + OFF_KLO);
      #pragma unroll
      for (int nt = 0; nt < 8; nt++) {
        float f0 = acc1[nt][0] * inv0, f1 = acc1[nt][1] * inv0;
        float f2 = acc1[nt][2] * inv1, f3 = acc1[nt][3] * inv1;
        ksum[2*nt]   += f0 + f2;
        ksum[2*nt+1] += f1 + f3;
        int col = nt*8 + cl2;
        int bi0 = r0       * (KSTR/2) + (col >> 1);
        int bi1 = (r0 + 8) * (KSTR/2) + (col >> 1);
        split_store(ph, pl, bi0, f0, f1);
        split_store(ph, pl, bi1, f2, f3);
      }
    }
    __syncthreads();

    // ---- stage 2: P[c,e] += K[c,px] @ X[e,px]^T over 128 px, bf16x3 ----
    const uint32_t b2off = sb + xbuf + b2term;
    #pragma unroll
    for (int ks = 0; ks < 8; ks++) {
      uint32_t ah[4], al[4];
      uint32_t astep = (uint32_t)(ks * 16 * KSTR) * 2;
      ldsm4t(ah, a2off + astep);
      ldsm4t(al, a2off + astep + 18432u);
      #pragma unroll
      for (int dbi = 0; dbi < 2; dbi++) {
        uint32_t bh[4], bl[4];
        uint32_t bo = (uint32_t)(dbi * 16 * XSTR + ks * 16) * 2;
        ldsm4(bh, b2off + bo);
        ldsm4(bl, b2off + bo + XLOD);
        mma16816(acc2[2*dbi],   ah, bh[0], bh[1]);
        mma16816(acc2[2*dbi],   ah, bl[0], bl[1]);
        mma16816(acc2[2*dbi],   al, bh[0], bh[1]);
        mma16816(acc2[2*dbi+1], ah, bh[2], bh[3]);
        mma16816(acc2[2*dbi+1], ah, bl[2], bl[3]);
        mma16816(acc2[2*dbi+1], al, bh[2], bh[3]);
      }
    }
    // no trailing barrier: X double-buffered (conv(t+1) hits other buffer);
    // K(t) rewritten only after next iteration's first barrier.
  }

  // ---- flush P ----
  float* pp = g_P + (size_t)b * CH * CH;
  const int c0 = c_base + (l >> 2);
  #pragma unroll
  for (int nt = 0; nt < 4; nt++)
    #pragma unroll
    for (int j = 0; j < 2; j++) {
      int d = d_base + nt*8 + cl2 + j;
      atomicAdd(pp + c0*CH + d,       acc2[nt][j]);
      atomicAdd(pp + (c0+8)*CH + d,   acc2[nt][2+j]);
    }

  // ---- flush kpsum: reduce over px-subgroups (lane bits 2..4), lanes 0-3 write ----
  #pragma unroll
  for (int i = 0; i < 16; i++) {
    float s = ksum[i];
    s += __shfl_xor_sync(0xffffffffu, s, 4);
    s += __shfl_xor_sync(0xffffffffu, s, 8);
    s += __shfl_xor_sync(0xffffffffu, s, 16);
    if (l < 4) {
      int ch = (i >> 1)*8 + cl2 + (i & 1);
      atomicAdd(g_kpsum + b*CH + ch, s);
    }
  }
}

// ============ ctx[b][c][d] = sum_e P[b][c][e] Wv[d][e] + kpsum[b][c] bv[d] ============
__global__ void __launch_bounds__(256) ctx_kernel(
    const float* __restrict__ Wv, const float* __restrict__ bv)
{
  __shared__ float Pt[64*68];   // [e][c]
  __shared__ float Wt[64*68];   // [e][d]
  __shared__ float kp[64], bvs[64];
  const int b = blockIdx.x;
  const int tid = threadIdx.x;
  const float* Pg = g_P + (size_t)b * 4096;

  for (int idx = tid; idx < 4096; idx += 256) {
    int r = idx >> 6, e = idx & 63;
    Pt[e*68 + r] = Pg[idx];
    Wt[e*68 + r] = Wv[idx];
  }
  if (tid < 64) { kp[tid] = g_kpsum[b*64 + tid]; bvs[tid] = bv[tid]; }
  __syncthreads();

  const int c0 = (tid >> 4) * 4;
  const int d0 = (tid & 15) * 4;
  float acc[4][4];
  #pragma unroll
  for (int i = 0; i < 4; i++)
    #pragma unroll
    for (int j = 0; j < 4; j++) acc[i][j] = 0.f;

  #pragma unroll 4
  for (int e = 0; e < 64; e++) {
    float4 pc = *(const float4*)&Pt[e*68 + c0];
    float4 wd = *(const float4*)&Wt[e*68 + d0];
    float p[4] = {pc.x, pc.y, pc.z, pc.w};
    float q[4] = {wd.x, wd.y, wd.z, wd.w};
    #pragma unroll
    for (int i = 0; i < 4; i++)
      #pragma unroll
      for (int j = 0; j < 4; j++) acc[i][j] += p[i] * q[j];
  }

  float* cp = g_context + (size_t)b * 4096;
  #pragma unroll
  for (int i = 0; i < 4; i++)
    #pragma unroll
    for (int j = 0; j < 4; j++)
      cp[(c0+i)*64 + d0+j] = acc[i][j] + kp[c0+i] * bvs[d0+j];
}

// dynw[b,i,j] = sum_m sigmoid(context[b,i,m]) * Wfc[i,j,m] + bfc[i,j]
__global__ void __launch_bounds__(128) dynw_kernel(
    const float* __restrict__ Wfc, const float* __restrict__ bfc)
{
  int warp = blockIdx.x * 4 + (threadIdx.x >> 5);   // 0..4095
  int lane = threadIdx.x & 31;
  int i = warp & 63;
  const float* ctx = g_context + (size_t)warp * 64;
  float a0 = 1.f / (1.f + __expf(-ctx[lane]));
  float a1 = 1.f / (1.f + __expf(-ctx[lane + 32]));
  #pragma unroll
  for (int j = 0; j < 9; j++) {
    float s = a0 * Wfc[(i*9 + j)*64 + lane] + a1 * Wfc[(i*9 + j)*64 + lane + 32];
    #pragma unroll
    for (int o = 16; o > 0; o >>= 1) s += __shfl_xor_sync(0xffffffffu, s, o);
    if (lane == 0) g_dynw[warp*9 + j] = s + bfc[i*9 + j];
  }
}

// depthwise 3x3, pad 1 — float4 per thread, 4 row-groups of 7 rows (round-6 proven)
#define TROWS 28
#define TS_STR 120
__global__ void __launch_bounds__(128) dwconv_kernel(
    const float* __restrict__ x, float* __restrict__ out)
{
  __shared__ float ts[(TROWS + 2) * TS_STR];   // data col s at idx s+4
  const int plane = blockIdx.x;                 // b*64 + c
  const int rb = blockIdx.y * TROWS;
  const float* xp = x + (size_t)plane * HWPIX;
  const int tid = threadIdx.x;

  // float4 fill: 30 rows x 28 float4
  for (int i = tid; i < 840; i += 128) {
    int r = i / 28, k = i - r * 28;
    int gr = rb - 1 + r;
    float4 v = make_float4(0.f, 0.f, 0.f, 0.f);
    if (gr >= 0 && gr < HH) v = __ldg((const float4*)(xp + (size_t)gr * WW) + k);
    *(float4*)&ts[r * TS_STR + 4 + 4*k] = v;
  }
  for (int i = tid; i < 30; i += 128) { ts[i*TS_STR + 3] = 0.f; ts[i*TS_STR + 116] = 0.f; }

  float w[9];
  const float* wp = g_dynw + (size_t)plane * 9;
  #pragma unroll
  for (int k = 0; k < 9; k++) w[k] = __ldg(wp + k);
  __syncthreads();

  if (tid < 112) {
    const int g  = tid / 28;         // row group 0..3 (7 rows each)
    const int c4 = tid - g * 28;     // float4 column 0..27
    const float* rp = ts + (g*7) * TS_STR + 4*c4 + 3;
    float  L0 = rp[0];  float4 F0 = *(const float4*)(rp + 1);  float R0 = rp[5];
    rp += TS_STR;
    float  L1 = rp[0];  float4 F1 = *(const float4*)(rp + 1);  float R1 = rp[5];
    float* op = out + (size_t)plane * HWPIX + (size_t)(rb + g*7) * WW + 4*c4;
    #pragma unroll
    for (int j = 0; j < 7; j++) {
      rp += TS_STR;
      float  L2 = rp[0];  float4 F2 = *(const float4*)(rp + 1);  float R2 = rp[5];
      float4 o;
      o.x = w[0]*L0   + w[1]*F0.x + w[2]*F0.y
          + w[3]*L1   + w[4]*F1.x + w[5]*F1.y
          + w[6]*L2   + w[7]*F2.x + w[8]*F2.y;
      o.y = w[0]*F0.x + w[1]*F0.y + w[2]*F0.z
          + w[3]*F1.x + w[4]*F1.y + w[5]*F1.z
          + w[6]*F2.x + w[7]*F2.y + w[8]*F2.z;
      o.z = w[0]*F0.y + w[1]*F0.z + w[2]*F0.w
          + w[3]*F1.y + w[4]*F1.z + w[5]*F1.w
          + w[6]*F2.y + w[7]*F2.z + w[8]*F2.w;
      o.w = w[0]*F0.z + w[1]*F0.w + w[2]*R0
          + w[3]*F1.z + w[4]*F1.w + w[5]*R1
          + w[6]*F2.z + w[7]*F2.w + w[8]*R2;
      *(float4*)op = o;
      op += WW;
      L0 = L1; F0 = F1; R0 = R1;
      L1 = L2; F1 = F2; R1 = R2;
    }
  }
}

extern "C" void kernel_launch(void* const* d_in, const int* in_sizes, int n_in,
                              void* d_out, int out_size)
{
  const float* x    = (const float*)d_in[0];
  const float* Wv   = (const float*)d_in[1];
  const float* bv   = (const float*)d_in[2];
  const float* Wm   = (const float*)d_in[3];
  const float* bm   = (const float*)d_in[4];
  const float* gma  = (const float*)d_in[5];
  const float* bta  = (const float*)d_in[6];
  const float* mu   = (const float*)d_in[7];
  const float* var  = (const float*)d_in[8];
  const float* Wfc  = (const float*)d_in[9];
  const float* bfc  = (const float*)d_in[10];
  float* out = (float*)d_out;

  cudaFuncSetAttribute(attn_p_mma,
                       cudaFuncAttributeMaxDynamicSharedMemorySize, SMEMB);

  zero_kernel<<<256, 256>>>();
  attn_p_mma<<<dim3(BLKX, BATCH), 256, SMEMB>>>(x, Wm, bm, gma, bta, mu, var);
  ctx_kernel<<<BATCH, 256>>>(Wv, bv);
  dynw_kernel<<<1024, 128>>>(Wfc, bfc);
  dwconv_kernel<<<dim3(BATCH * CH, HH / TROWS), 128>>>(x, out);
}

// round 11
// speedup vs baseline: 1.3130x; 1.1151x over previous
#include <cuda_runtime.h>
#include <cuda_bf16.h>
#include <cstdint>

#define BATCH 64
#define CH 64
#define HH 112
#define WW 112
#define HWPIX (HH*WW)          // 12544
#define NP 128                 // pixels per tile
#define TPB 7
#define BLKX 14                // 14*7*128 = 12544
#define EPSV 1e-5f

// device scratch (no cudaMalloc allowed)
__device__ float g_P[BATCH*CH*CH];         // [b][c][e] = sum_p k_c(p) x_e(p)
__device__ float g_kpsum[BATCH*CH];        // [b][c]    = sum_p k_c(p)
__device__ float g_context[BATCH*CH*CH];   // [b][c][d]
__device__ float g_dynw[BATCH*CH*9];       // [b*c][9]

// ---------------- smem layout (bytes) ----------------
// X : [64 ch][136 stride] bf16 (hi,lo), SINGLE buffer (stage-1 A + stage-2 B)
// W : [64 out][72 stride] bf16 (hi,lo)  (Wm * bnscale)
// K : [128 px][72 stride] bf16 (hi,lo)  (softmaxed key)
#define XSTR  136
#define WSTR  72
#define KSTR  72
#define OFF_XHI  0             // lo at +17408
#define XLOD     17408
#define OFF_WHI  34816         // 9216 bytes
#define OFF_WLO  44032
#define OFF_KHI  53248         // 18432 bytes
#define OFF_KLO  71680
#define OFF_KSH  90112         // 64 floats BN shift
#define SMEMB    90368

// ---------------- helpers ----------------
__device__ __forceinline__ uint32_t smem_u32(const void* p){
  uint32_t a;
  asm("{ .reg .u64 t; cvta.to.shared.u64 t, %1; cvt.u32.u64 %0, t; }" : "=r"(a) : "l"(p));
  return a;
}
__device__ __forceinline__ void ldsm4(uint32_t* r, uint32_t addr){
  asm volatile("ldmatrix.sync.aligned.m8n8.x4.shared.b16 {%0,%1,%2,%3}, [%4];"
    : "=r"(r[0]), "=r"(r[1]), "=r"(r[2]), "=r"(r[3]) : "r"(addr));
}
__device__ __forceinline__ void ldsm4t(uint32_t* r, uint32_t addr){
  asm volatile("ldmatrix.sync.aligned.m8n8.x4.trans.shared.b16 {%0,%1,%2,%3}, [%4];"
    : "=r"(r[0]), "=r"(r[1]), "=r"(r[2]), "=r"(r[3]) : "r"(addr));
}
__device__ __forceinline__ void mma16816(float* d, const uint32_t* a, uint32_t b0, uint32_t b1){
  asm volatile("mma.sync.aligned.m16n8k16.row.col.f32.bf16.bf16.f32 "
    "{%0,%1,%2,%3}, {%4,%5,%6,%7}, {%8,%9}, {%0,%1,%2,%3};"
    : "+f"(d[0]), "+f"(d[1]), "+f"(d[2]), "+f"(d[3])
    : "r"(a[0]), "r"(a[1]), "r"(a[2]), "r"(a[3]), "r"(b0), "r"(b1));
}
// truncation split: hi = bits & 0xffff0000 (exact bf16), lo = rn_bf16(f - hi)
__device__ __forceinline__ void split_store(uint32_t* ph, uint32_t* pl, int bi,
                                            float f0, float f1){
  uint32_t u0 = __float_as_uint(f0), u1 = __float_as_uint(f1);
  ph[bi] = __byte_perm(u0, u1, 0x7632);                 // [hi16(u0), hi16(u1)]
  float h0 = __uint_as_float(u0 & 0xffff0000u);
  float h1 = __uint_as_float(u1 & 0xffff0000u);
  __nv_bfloat162 t = __floats2bfloat162_rn(f0 - h0, f1 - h1);
  pl[bi] = *(uint32_t*)&t;
}

__global__ void __launch_bounds__(256) zero_kernel(){
  int i = blockIdx.x * blockDim.x + threadIdx.x;   // 65536 float4
  ((float4*)g_P)[i] = make_float4(0.f,0.f,0.f,0.f);
  if (i < 1024) ((float4*)g_kpsum)[i] = make_float4(0.f,0.f,0.f,0.f);
}

// ============ fused K-attention: P = softmax(BN(Wm X)) @ X^T, bf16x3 HMMA ============
__global__ void __launch_bounds__(256, 2) attn_p_mma(
    const float* __restrict__ x,
    const float* __restrict__ Wm, const float* __restrict__ bm,
    const float* __restrict__ gma, const float* __restrict__ bta,
    const float* __restrict__ mu,  const float* __restrict__ var)
{
  extern __shared__ char smc[];
  const uint32_t sb = smem_u32(smc);
  const int tid = threadIdx.x;
  const int w   = tid >> 5;        // warp 0..7
  const int l   = tid & 31;
  const int b   = blockIdx.y;

  const int lk = (l & 7) + 8 * (l >> 4);     // ldmatrix row term
  const int lc = 8 * ((l >> 3) & 1);         // ldmatrix col term
  const int cl2 = 2 * (l & 3);

  const float* xb = x + (size_t)b * CH * HWPIX;

  // ---- prefetch X tile 0 into registers ----
  float4 xr[8];
  {
    const int n0 = blockIdx.x * TPB * NP;
    #pragma unroll
    for (int i = 0; i < 8; i++) {
      int f4 = tid + 256 * i;
      int chn = f4 >> 5, pxf = f4 & 31;
      xr[i] = __ldg((const float4*)(xb + (size_t)chn * HWPIX + n0) + pxf);
    }
  }

  // ---- load W = Wm * bnscale (64 rows), bf16 hi/lo, once ----
  {
    uint32_t* ph = (uint32_t*)(smc + OFF_WHI);
    uint32_t* pl = (uint32_t*)(smc + OFF_WLO);
    #pragma unroll
    for (int i = 0; i < 4; i++) {
      int f4 = tid + 256 * i;        // 1024 float4
      int o  = f4 >> 4;
      int c4 = (f4 & 15) * 4;
      float4 v = __ldg((const float4*)(Wm + o*64 + c4));
      float s = __ldg(gma + o) * rsqrtf(__ldg(var + o) + EPSV);
      v.x *= s; v.y *= s; v.z *= s; v.w *= s;
      int bi = o * (WSTR/2) + (c4 >> 1);
      split_store(ph, pl, bi,     v.x, v.y);
      split_store(ph, pl, bi + 1, v.z, v.w);
    }
  }
  // BN shift (folded) into smem
  if (tid < CH) {
    float sc = __ldg(gma + tid) * rsqrtf(__ldg(var + tid) + EPSV);
    *(float*)(smc + OFF_KSH + tid*4) =
        (__ldg(bm + tid) - __ldg(mu + tid)) * sc + __ldg(bta + tid);
  }

  // ---- persistent accumulators: P tile 16x32 per warp + kpsum partials ----
  const int c_base = (w >> 1) * 16;
  const int d_base = (w & 1) * 32;
  float acc2[4][4];
  #pragma unroll
  for (int i = 0; i < 4; i++)
    #pragma unroll
    for (int j = 0; j < 4; j++) acc2[i][j] = 0.f;
  float ksum[16];
  #pragma unroll
  for (int i = 0; i < 16; i++) ksum[i] = 0.f;

  // ldmatrix base byte offsets (X single buffer)
  const uint32_t a1off = sb + OFF_XHI + (uint32_t)(lk*XSTR + 16*w + lc) * 2;
  const uint32_t b1off = sb + OFF_WHI + (uint32_t)(lk*WSTR + lc) * 2;
  const uint32_t a2off = sb + OFF_KHI + (uint32_t)(lk*KSTR + c_base + lc) * 2;
  const uint32_t b2off = sb + OFF_XHI + (uint32_t)((d_base + lk)*XSTR + lc) * 2;

  for (int t = 0; t < TPB; t++) {
    // ---- conv X(t) from regs into Xsm (stage2(t-1) finished at bar3) ----
    {
      uint32_t* ph = (uint32_t*)(smc + OFF_XHI);
      uint32_t* pl = (uint32_t*)(smc + OFF_XHI + XLOD);
      #pragma unroll
      for (int i = 0; i < 8; i++) {
        int f4  = tid + 256 * i;
        int chn = f4 >> 5, pxf = f4 & 31;
        int bi = chn * (XSTR/2) + pxf * 2;
        split_store(ph, pl, bi,     xr[i].x, xr[i].y);
        split_store(ph, pl, bi + 1, xr[i].z, xr[i].w);
      }
    }
    __syncthreads();   // bar1: Xsm(t) (+W on t=0) visible

    // ---- prefetch X(t+1) (hidden behind stage-1 MMAs) ----
    if (t + 1 < TPB) {
      const int n1 = (blockIdx.x * TPB + t + 1) * NP;
      #pragma unroll
      for (int i = 0; i < 8; i++) {
        int f4 = tid + 256 * i;
        int chn = f4 >> 5, pxf = f4 & 31;
        xr[i] = __ldg((const float4*)(xb + (size_t)chn * HWPIX + n1) + pxf);
      }
    }

    // ---- stage 1: logits[16 px of warp][64 ch] = X @ W^T, bf16x3 ----
    float acc1[8][4];
    #pragma unroll
    for (int i = 0; i < 8; i++)
      #pragma unroll
      for (int j = 0; j < 4; j++) acc1[i][j] = 0.f;

    #pragma unroll
    for (int ks = 0; ks < 4; ks++) {
      uint32_t ah[4], al[4];
      uint32_t astep = (uint32_t)(ks * 16 * XSTR) * 2;
      ldsm4t(ah, a1off + astep);
      ldsm4t(al, a1off + astep + XLOD);
      #pragma unroll
      for (int nb = 0; nb < 4; nb++) {
        uint32_t bh[4], bl[4];
        uint32_t bo = (uint32_t)((nb*16) * WSTR + ks*16) * 2;
        ldsm4(bh, b1off + bo);
        ldsm4(bl, b1off + bo + 9216u);
        mma16816(acc1[2*nb],   ah, bh[0], bh[1]);
        mma16816(acc1[2*nb],   ah, bl[0], bl[1]);
        mma16816(acc1[2*nb],   al, bh[0], bh[1]);
        mma16816(acc1[2*nb+1], ah, bh[2], bh[3]);
        mma16816(acc1[2*nb+1], ah, bl[2], bl[3]);
        mma16816(acc1[2*nb+1], al, bh[2], bh[3]);
      }
    }

    // ---- softmax over 64 channels (warp-local, 2 px per thread) ----
    const float* ksm = (const float*)(smc + OFF_KSH);
    float m0 = -1e30f, m1 = -1e30f;
    #pragma unroll
    for (int nt = 0; nt < 8; nt++)
      #pragma unroll
      for (int j = 0; j < 2; j++) {
        float sh = ksm[nt*8 + cl2 + j];
        acc1[nt][j]   += sh;
        acc1[nt][2+j] += sh;
        m0 = fmaxf(m0, acc1[nt][j]);
        m1 = fmaxf(m1, acc1[nt][2+j]);
      }
    m0 = fmaxf(m0, __shfl_xor_sync(0xffffffffu, m0, 1));
    m0 = fmaxf(m0, __shfl_xor_sync(0xffffffffu, m0, 2));
    m1 = fmaxf(m1, __shfl_xor_sync(0xffffffffu, m1, 1));
    m1 = fmaxf(m1, __shfl_xor_sync(0xffffffffu, m1, 2));
    float s0 = 0.f, s1 = 0.f;
    #pragma unroll
    for (int nt = 0; nt < 8; nt++)
      #pragma unroll
      for (int j = 0; j < 2; j++) {
        acc1[nt][j]   = __expf(acc1[nt][j]   - m0); s0 += acc1[nt][j];
        acc1[nt][2+j] = __expf(acc1[nt][2+j] - m1); s1 += acc1[nt][2+j];
      }
    s0 += __shfl_xor_sync(0xffffffffu, s0, 1);
    s0 += __shfl_xor_sync(0xffffffffu, s0, 2);
    s1 += __shfl_xor_sync(0xffffffffu, s1, 1);
    s1 += __shfl_xor_sync(0xffffffffu, s1, 2);
    const float inv0 = 1.f / s0, inv1 = 1.f / s1;

    // ---- write K smem [px][64 ch] bf16 hi/lo + accumulate kpsum ----
    {
      const int r0 = 16*w + (l >> 2);
      uint32_t* ph = (uint32_t*)(smc + OFF_KHI);
      uint32_t* pl = (uint32_t*)(smc + OFF_KLO);
      #pragma unroll
      for (int nt = 0; nt < 8; nt++) {
        float f0 = acc1[nt][0] * inv0, f1 = acc1[nt][1] * inv0;
        float f2 = acc1[nt][2] * inv1, f3 = acc1[nt][3] * inv1;
        ksum[2*nt]   += f0 + f2;
        ksum[2*nt+1] += f1 + f3;
        int col = nt*8 + cl2;
        int bi0 = r0       * (KSTR/2) + (col >> 1);
        int bi1 = (r0 + 8) * (KSTR/2) + (col >> 1);
        split_store(ph, pl, bi0, f0, f1);
        split_store(ph, pl, bi1, f2, f3);
      }
    }
    __syncthreads();   // bar2: K(t) visible

    // ---- stage 2: P[c,e] += K[c,px] @ X[e,px]^T over 128 px, bf16x3 ----
    #pragma unroll
    for (int ks = 0; ks < 8; ks++) {
      uint32_t ah[4], al[4];
      uint32_t astep = (uint32_t)(ks * 16 * KSTR) * 2;
      ldsm4t(ah, a2off + astep);
      ldsm4t(al, a2off + astep + 18432u);
      #pragma unroll
      for (int dbi = 0; dbi < 2; dbi++) {
        uint32_t bh[4], bl[4];
        uint32_t bo = (uint32_t)(dbi * 16 * XSTR + ks * 16) * 2;
        ldsm4(bh, b2off + bo);
        ldsm4(bl, b2off + bo + XLOD);
        mma16816(acc2[2*dbi],   ah, bh[0], bh[1]);
        mma16816(acc2[2*dbi],   ah, bl[0], bl[1]);
        mma16816(acc2[2*dbi],   al, bh[0], bh[1]);
        mma16816(acc2[2*dbi+1], ah, bh[2], bh[3]);
        mma16816(acc2[2*dbi+1], ah, bl[2], bl[3]);
        mma16816(acc2[2*dbi+1], al, bh[2], bh[3]);
      }
    }
    __syncthreads();   // bar3: stage2(t) done -> Xsm/K free for next conv
  }

  // ---- flush P ----
  float* pp = g_P + (size_t)b * CH * CH;
  const int c0 = c_base + (l >> 2);
  #pragma unroll
  for (int nt = 0; nt < 4; nt++)
    #pragma unroll
    for (int j = 0; j < 2; j++) {
      int d = d_base + nt*8 + cl2 + j;
      atomicAdd(pp + c0*CH + d,       acc2[nt][j]);
      atomicAdd(pp + (c0+8)*CH + d,   acc2[nt][2+j]);
    }

  // ---- flush kpsum ----
  #pragma unroll
  for (int i = 0; i < 16; i++) {
    float s = ksum[i];
    s += __shfl_xor_sync(0xffffffffu, s, 4);
    s += __shfl_xor_sync(0xffffffffu, s, 8);
    s += __shfl_xor_sync(0xffffffffu, s, 16);
    if (l < 4) {
      int ch = (i >> 1)*8 + cl2 + (i & 1);
      atomicAdd(g_kpsum + b*CH + ch, s);
    }
  }
}

// ============ ctx[b][c][d] = sum_e P[b][c][e] Wv[d][e] + kpsum[b][c] bv[d] ============
__global__ void __launch_bounds__(256) ctx_kernel(
    const float* __restrict__ Wv, const float* __restrict__ bv)
{
  __shared__ float Pt[64*68];   // [e][c]
  __shared__ float Wt[64*68];   // [e][d]
  __shared__ float kp[64], bvs[64];
  const int b = blockIdx.x;
  const int tid = threadIdx.x;
  const float* Pg = g_P + (size_t)b * 4096;

  for (int idx = tid; idx < 4096; idx += 256) {
    int r = idx >> 6, e = idx & 63;
    Pt[e*68 + r] = Pg[idx];
    Wt[e*68 + r] = Wv[idx];
  }
  if (tid < 64) { kp[tid] = g_kpsum[b*64 + tid]; bvs[tid] = bv[tid]; }
  __syncthreads();

  const int c0 = (tid >> 4) * 4;
  const int d0 = (tid & 15) * 4;
  float acc[4][4];
  #pragma unroll
  for (int i = 0; i < 4; i++)
    #pragma unroll
    for (int j = 0; j < 4; j++) acc[i][j] = 0.f;

  #pragma unroll 4
  for (int e = 0; e < 64; e++) {
    float4 pc = *(const float4*)&Pt[e*68 + c0];
    float4 wd = *(const float4*)&Wt[e*68 + d0];
    float p[4] = {pc.x, pc.y, pc.z, pc.w};
    float q[4] = {wd.x, wd.y, wd.z, wd.w};
    #pragma unroll
    for (int i = 0; i < 4; i++)
      #pragma unroll
      for (int j = 0; j < 4; j++) acc[i][j] += p[i] * q[j];
  }

  float* cp = g_context + (size_t)b * 4096;
  #pragma unroll
  for (int i = 0; i < 4; i++)
    #pragma unroll
    for (int j = 0; j < 4; j++)
      cp[(c0+i)*64 + d0+j] = acc[i][j] + kp[c0+i] * bvs[d0+j];
}

// dynw[b,i,j] = sum_m sigmoid(context[b,i,m]) * Wfc[i,j,m] + bfc[i,j]
__global__ void __launch_bounds__(128) dynw_kernel(
    const float* __restrict__ Wfc, const float* __restrict__ bfc)
{
  int warp = blockIdx.x * 4 + (threadIdx.x >> 5);   // 0..4095
  int lane = threadIdx.x & 31;
  int i = warp & 63;
  const float* ctx = g_context + (size_t)warp * 64;
  float a0 = 1.f / (1.f + __expf(-ctx[lane]));
  float a1 = 1.f / (1.f + __expf(-ctx[lane + 32]));
  #pragma unroll
  for (int j = 0; j < 9; j++) {
    float s = a0 * Wfc[(i*9 + j)*64 + lane] + a1 * Wfc[(i*9 + j)*64 + lane + 32];
    #pragma unroll
    for (int o = 16; o > 0; o >>= 1) s += __shfl_xor_sync(0xffffffffu, s, o);
    if (lane == 0) g_dynw[warp*9 + j] = s + bfc[i*9 + j];
  }
}

// depthwise 3x3, pad 1 — float4/thread, halo via shfl (no smem padding)
#define TROWS 28
__global__ void __launch_bounds__(128) dwconv_kernel(
    const float* __restrict__ x, float* __restrict__ out)
{
  __shared__ float ts[30 * 112];
  const int plane = blockIdx.x;                 // b*64 + c
  const int rb = blockIdx.y * TROWS;
  const float* xp = x + (size_t)plane * HWPIX;
  const int tid = threadIdx.x;
  const int g  = tid >> 5;        // row group 0..3
  const int c4 = tid & 31;        // float4 column (0..27 valid)

  // fill: rows g, g+4, ... < 30 ; each row 28 float4 coalesced
  for (int r = g; r < 30; r += 4) {
    int gr = rb - 1 + r;
    if (c4 < 28) {
      float4 v = make_float4(0.f, 0.f, 0.f, 0.f);
      if (gr >= 0 && gr < HH) v = __ldg((const float4*)(xp + (size_t)gr * WW) + c4);
      *(float4*)&ts[r * 112 + 4 * c4] = v;
    }
  }

  float w[9];
  const float* wp = g_dynw + (size_t)plane * 9;
  #pragma unroll
  for (int k = 0; k < 9; k++) w[k] = __ldg(wp + k);
  __syncthreads();

  const int cc = (c4 < 28) ? c4 : 27;           // clamp for inactive lanes
  const float* rp = ts + (g * 7) * 112 + 4 * cc;

  float4 F0 = *(const float4*)rp;
  float4 F1 = *(const float4*)(rp + 112);
  float L0 = __shfl_up_sync(0xffffffffu, F0.w, 1);   if (c4 == 0)  L0 = 0.f;
  float R0 = __shfl_down_sync(0xffffffffu, F0.x, 1); if (c4 >= 27) R0 = 0.f;
  float L1 = __shfl_up_sync(0xffffffffu, F1.w, 1);   if (c4 == 0)  L1 = 0.f;
  float R1 = __shfl_down_sync(0xffffffffu, F1.x, 1); if (c4 >= 27) R1 = 0.f;

  float* op = out + (size_t)plane * HWPIX + (size_t)(rb + g*7) * WW + 4*c4;
  #pragma unroll
  for (int j = 0; j < 7; j++) {
    float4 F2 = *(const float4*)(rp + (j + 2) * 112);
    float L2 = __shfl_up_sync(0xffffffffu, F2.w, 1);   if (c4 == 0)  L2 = 0.f;
    float R2 = __shfl_down_sync(0xffffffffu, F2.x, 1); if (c4 >= 27) R2 = 0.f;
    float4 o;
    o.x = w[0]*L0   + w[1]*F0.x + w[2]*F0.y
        + w[3]*L1   + w[4]*F1.x + w[5]*F1.y
        + w[6]*L2   + w[7]*F2.x + w[8]*F2.y;
    o.y = w[0]*F0.x + w[1]*F0.y + w[2]*F0.z
        + w[3]*F1.x + w[4]*F1.y + w[5]*F1.z
        + w[6]*F2.x + w[7]*F2.y + w[8]*F2.z;
    o.z = w[0]*F0.y + w[1]*F0.z + w[2]*F0.w
        + w[3]*F1.y + w[4]*F1.z + w[5]*F1.w
        + w[6]*F2.y + w[7]*F2.z + w[8]*F2.w;
    o.w = w[0]*F0.z + w[1]*F0.w + w[2]*R0
        + w[3]*F1.z + w[4]*F1.w + w[5]*R1
        + w[6]*F2.z + w[7]*F2.w + w[8]*R2;
    if (c4 < 28) *(float4*)op = o;
    op += WW;
    L0 = L1; F0 = F1; R0 = R1;
    L1 = L2; F1 = F2; R1 = R2;
  }
}

extern "C" void kernel_launch(void* const* d_in, const int* in_sizes, int n_in,
                              void* d_out, int out_size)
{
  const float* x    = (const float*)d_in[0];
  const float* Wv   = (const float*)d_in[1];
  const float* bv   = (const float*)d_in[2];
  const float* Wm   = (const float*)d_in[3];
  const float* bm   = (const float*)d_in[4];
  const float* gma  = (const float*)d_in[5];
  const float* bta  = (const float*)d_in[6];
  const float* mu   = (const float*)d_in[7];
  const float* var  = (const float*)d_in[8];
  const float* Wfc  = (const float*)d_in[9];
  const float* bfc  = (const float*)d_in[10];
  float* out = (float*)d_out;

  cudaFuncSetAttribute(attn_p_mma,
                       cudaFuncAttributeMaxDynamicSharedMemorySize, SMEMB);

  zero_kernel<<<256, 256>>>();
  attn_p_mma<<<dim3(BLKX, BATCH), 256, SMEMB>>>(x, Wm, bm, gma, bta, mu, var);
  ctx_kernel<<<BATCH, 256>>>(Wv, bv);
  dynw_kernel<<<1024, 128>>>(Wfc, bfc);
  dwconv_kernel<<<dim3(BATCH * CH, HH / TROWS), 128>>>(x, out);
}

// round 13
// speedup vs baseline: 1.3157x; 1.0021x over previous
#include <cuda_runtime.h>
#include <cuda_bf16.h>
#include <cstdint>

#define BATCH 64
#define CH 64
#define HH 112
#define WW 112
#define HWPIX (HH*WW)          // 12544
#define NP 128                 // pixels per tile
#define TPB 7
#define BLKX 14                // 14*7*128 = 12544
#define EPSV 1e-5f

// device scratch (no cudaMalloc allowed)
__device__ float g_P[BATCH*CH*CH];         // [b][c][e] = sum_p k_c(p) x_e(p)
__device__ float g_kpsum[BATCH*CH];        // [b][c]    = sum_p k_c(p)
__device__ float g_context[BATCH*CH*CH];   // [b][c][d]
__device__ float g_dynw[BATCH*CH*9];       // [b*c][9]

// ---------------- smem layout (bytes) ----------------
// X : [64 ch][136 stride] bf16 (hi,lo), SINGLE buffer (stage-1 A + stage-2 B)
// W : [64 out][72 stride] bf16 (hi,lo)  (Wm * bnscale)
// K : [128 px][72 stride] bf16 (hi,lo)  (softmaxed key)
#define XSTR  136
#define WSTR  72
#define KSTR  72
#define OFF_XHI  0             // lo at +17408
#define XLOD     17408
#define OFF_WHI  34816         // 9216 bytes
#define OFF_WLO  44032
#define OFF_KHI  53248         // 18432 bytes
#define OFF_KLO  71680
#define OFF_KSH  90112         // 64 floats BN shift
#define SMEMB    90368

// ---------------- helpers ----------------
__device__ __forceinline__ uint32_t smem_u32(const void* p){
  uint32_t a;
  asm("{ .reg .u64 t; cvta.to.shared.u64 t, %1; cvt.u32.u64 %0, t; }" : "=r"(a) : "l"(p));
  return a;
}
__device__ __forceinline__ void ldsm4(uint32_t* r, uint32_t addr){
  asm volatile("ldmatrix.sync.aligned.m8n8.x4.shared.b16 {%0,%1,%2,%3}, [%4];"
    : "=r"(r[0]), "=r"(r[1]), "=r"(r[2]), "=r"(r[3]) : "r"(addr));
}
__device__ __forceinline__ void ldsm4t(uint32_t* r, uint32_t addr){
  asm volatile("ldmatrix.sync.aligned.m8n8.x4.trans.shared.b16 {%0,%1,%2,%3}, [%4];"
    : "=r"(r[0]), "=r"(r[1]), "=r"(r[2]), "=r"(r[3]) : "r"(addr));
}
__device__ __forceinline__ void mma16816(float* d, const uint32_t* a, uint32_t b0, uint32_t b1){
  asm volatile("mma.sync.aligned.m16n8k16.row.col.f32.bf16.bf16.f32 "
    "{%0,%1,%2,%3}, {%4,%5,%6,%7}, {%8,%9}, {%0,%1,%2,%3};"
    : "+f"(d[0]), "+f"(d[1]), "+f"(d[2]), "+f"(d[3])
    : "r"(a[0]), "r"(a[1]), "r"(a[2]), "r"(a[3]), "r"(b0), "r"(b1));
}
// truncation split: hi = bits & 0xffff0000 (exact bf16), lo = rn_bf16(f - hi)
__device__ __forceinline__ void split_store(uint32_t* ph, uint32_t* pl, int bi,
                                            float f0, float f1){
  uint32_t u0 = __float_as_uint(f0), u1 = __float_as_uint(f1);
  ph[bi] = __byte_perm(u0, u1, 0x7632);                 // [hi16(u0), hi16(u1)]
  float h0 = __uint_as_float(u0 & 0xffff0000u);
  float h1 = __uint_as_float(u1 & 0xffff0000u);
  __nv_bfloat162 t = __floats2bfloat162_rn(f0 - h0, f1 - h1);
  pl[bi] = *(uint32_t*)&t;
}
// 4-element variant: one STS.64 to hi plane, one STS.64 to lo plane (bi even, 8B aligned)
__device__ __forceinline__ void split_store2(uint32_t* ph, uint32_t* pl, int bi,
                                             float f0, float f1, float f2, float f3){
  uint32_t u0 = __float_as_uint(f0), u1 = __float_as_uint(f1);
  uint32_t u2 = __float_as_uint(f2), u3 = __float_as_uint(f3);
  uint2 h;
  h.x = __byte_perm(u0, u1, 0x7632);
  h.y = __byte_perm(u2, u3, 0x7632);
  *(uint2*)(ph + bi) = h;
  float h0 = __uint_as_float(u0 & 0xffff0000u);
  float h1 = __uint_as_float(u1 & 0xffff0000u);
  float h2 = __uint_as_float(u2 & 0xffff0000u);
  float h3 = __uint_as_float(u3 & 0xffff0000u);
  __nv_bfloat162 t0 = __floats2bfloat162_rn(f0 - h0, f1 - h1);
  __nv_bfloat162 t1 = __floats2bfloat162_rn(f2 - h2, f3 - h3);
  uint2 lo;
  lo.x = *(uint32_t*)&t0;
  lo.y = *(uint32_t*)&t1;
  *(uint2*)(pl + bi) = lo;
}

__global__ void __launch_bounds__(256) zero_kernel(){
  int i = blockIdx.x * blockDim.x + threadIdx.x;   // 65536 float4
  ((float4*)g_P)[i] = make_float4(0.f,0.f,0.f,0.f);
  if (i < 1024) ((float4*)g_kpsum)[i] = make_float4(0.f,0.f,0.f,0.f);
}

// ============ fused K-attention: P = softmax(BN(Wm X)) @ X^T, bf16x3 HMMA ============
__global__ void __launch_bounds__(256, 2) attn_p_mma(
    const float* __restrict__ x,
    const float* __restrict__ Wm, const float* __restrict__ bm,
    const float* __restrict__ gma, const float* __restrict__ bta,
    const float* __restrict__ mu,  const float* __restrict__ var)
{
  extern __shared__ char smc[];
  const uint32_t sb = smem_u32(smc);
  const int tid = threadIdx.x;
  const int w   = tid >> 5;        // warp 0..7
  const int l   = tid & 31;
  const int b   = blockIdx.y;

  const int lk = (l & 7) + 8 * (l >> 4);     // ldmatrix row term
  const int lc = 8 * ((l >> 3) & 1);         // ldmatrix col term
  const int cl2 = 2 * (l & 3);

  const float* xb = x + (size_t)b * CH * HWPIX;

  // ---- prefetch X tile 0 into registers ----
  float4 xr[8];
  {
    const int n0 = blockIdx.x * TPB * NP;
    #pragma unroll
    for (int i = 0; i < 8; i++) {
      int f4 = tid + 256 * i;
      int chn = f4 >> 5, pxf = f4 & 31;
      xr[i] = __ldg((const float4*)(xb + (size_t)chn * HWPIX + n0) + pxf);
    }
  }

  // ---- load W = Wm * bnscale (64 rows), bf16 hi/lo, once ----
  {
    uint32_t* ph = (uint32_t*)(smc + OFF_WHI);
    uint32_t* pl = (uint32_t*)(smc + OFF_WLO);
    #pragma unroll
    for (int i = 0; i < 4; i++) {
      int f4 = tid + 256 * i;        // 1024 float4
      int o  = f4 >> 4;
      int c4 = (f4 & 15) * 4;
      float4 v = __ldg((const float4*)(Wm + o*64 + c4));
      float s = __ldg(gma + o) * rsqrtf(__ldg(var + o) + EPSV);
      v.x *= s; v.y *= s; v.z *= s; v.w *= s;
      int bi = o * (WSTR/2) + (c4 >> 1);
      split_store2(ph, pl, bi, v.x, v.y, v.z, v.w);
    }
  }
  // BN shift (folded) into smem
  if (tid < CH) {
    float sc = __ldg(gma + tid) * rsqrtf(__ldg(var + tid) + EPSV);
    *(float*)(smc + OFF_KSH + tid*4) =
        (__ldg(bm + tid) - __ldg(mu + tid)) * sc + __ldg(bta + tid);
  }

  // ---- persistent accumulators: P tile 16x32 per warp + kpsum partials ----
  const int c_base = (w >> 1) * 16;
  const int d_base = (w & 1) * 32;
  float acc2[4][4];
  #pragma unroll
  for (int i = 0; i < 4; i++)
    #pragma unroll
    for (int j = 0; j < 4; j++) acc2[i][j] = 0.f;
  float ksum[16];
  #pragma unroll
  for (int i = 0; i < 16; i++) ksum[i] = 0.f;

  // ldmatrix base byte offsets (X single buffer)
  const uint32_t a1off = sb + OFF_XHI + (uint32_t)(lk*XSTR + 16*w + lc) * 2;
  const uint32_t b1off = sb + OFF_WHI + (uint32_t)(lk*WSTR + lc) * 2;
  const uint32_t a2off = sb + OFF_KHI + (uint32_t)(lk*KSTR + c_base + lc) * 2;
  const uint32_t b2off = sb + OFF_XHI + (uint32_t)((d_base + lk)*XSTR + lc) * 2;

  #pragma unroll 1
  for (int t = 0; t < TPB; t++) {
    // ---- conv X(t) from regs into Xsm (stage2(t-1) finished at bar3) ----
    {
      uint32_t* ph = (uint32_t*)(smc + OFF_XHI);
      uint32_t* pl = (uint32_t*)(smc + OFF_XHI + XLOD);
      #pragma unroll
      for (int i = 0; i < 8; i++) {
        int f4  = tid + 256 * i;
        int chn = f4 >> 5, pxf = f4 & 31;
        int bi = chn * (XSTR/2) + pxf * 2;
        split_store2(ph, pl, bi, xr[i].x, xr[i].y, xr[i].z, xr[i].w);
      }
    }
    __syncthreads();   // bar1: Xsm(t) (+W on t=0) visible

    // ---- prefetch X(t+1) (hidden behind stage-1 MMAs) ----
    if (t + 1 < TPB) {
      const int n1 = (blockIdx.x * TPB + t + 1) * NP;
      #pragma unroll
      for (int i = 0; i < 8; i++) {
        int f4 = tid + 256 * i;
        int chn = f4 >> 5, pxf = f4 & 31;
        xr[i] = __ldg((const float4*)(xb + (size_t)chn * HWPIX + n1) + pxf);
      }
    }

    // ---- stage 1: logits[16 px of warp][64 ch] = X @ W^T, bf16x3 ----
    float acc1[8][4];
    #pragma unroll
    for (int i = 0; i < 8; i++)
      #pragma unroll
      for (int j = 0; j < 4; j++) acc1[i][j] = 0.f;

    #pragma unroll
    for (int ks = 0; ks < 4; ks++) {
      uint32_t ah[4], al[4];
      uint32_t astep = (uint32_t)(ks * 16 * XSTR) * 2;
      ldsm4t(ah, a1off + astep);
      ldsm4t(al, a1off + astep + XLOD);
      #pragma unroll
      for (int nb = 0; nb < 4; nb++) {
        uint32_t bh[4], bl[4];
        uint32_t bo = (uint32_t)((nb*16) * WSTR + ks*16) * 2;
        ldsm4(bh, b1off + bo);
        ldsm4(bl, b1off + bo + 9216u);
        mma16816(acc1[2*nb],   ah, bh[0], bh[1]);
        mma16816(acc1[2*nb],   ah, bl[0], bl[1]);
        mma16816(acc1[2*nb],   al, bh[0], bh[1]);
        mma16816(acc1[2*nb+1], ah, bh[2], bh[3]);
        mma16816(acc1[2*nb+1], ah, bl[2], bl[3]);
        mma16816(acc1[2*nb+1], al, bh[2], bh[3]);
      }
    }

    // ---- softmax over 64 channels (warp-local, 2 px per thread) ----
    const float* ksm = (const float*)(smc + OFF_KSH);
    float m0 = -1e30f, m1 = -1e30f;
    #pragma unroll
    for (int nt = 0; nt < 8; nt++)
      #pragma unroll
      for (int j = 0; j < 2; j++) {
        float sh = ksm[nt*8 + cl2 + j];
        acc1[nt][j]   += sh;
        acc1[nt][2+j] += sh;
        m0 = fmaxf(m0, acc1[nt][j]);
        m1 = fmaxf(m1, acc1[nt][2+j]);
      }
    m0 = fmaxf(m0, __shfl_xor_sync(0xffffffffu, m0, 1));
    m0 = fmaxf(m0, __shfl_xor_sync(0xffffffffu, m0, 2));
    m1 = fmaxf(m1, __shfl_xor_sync(0xffffffffu, m1, 1));
    m1 = fmaxf(m1, __shfl_xor_sync(0xffffffffu, m1, 2));
    float s0 = 0.f, s1 = 0.f;
    #pragma unroll
    for (int nt = 0; nt < 8; nt++)
      #pragma unroll
      for (int j = 0; j < 2; j++) {
        acc1[nt][j]   = __expf(acc1[nt][j]   - m0); s0 += acc1[nt][j];
        acc1[nt][2+j] = __expf(acc1[nt][2+j] - m1); s1 += acc1[nt][2+j];
      }
    s0 += __shfl_xor_sync(0xffffffffu, s0, 1);
    s0 += __shfl_xor_sync(0xffffffffu, s0, 2);
    s1 += __shfl_xor_sync(0xffffffffu, s1, 1);
    s1 += __shfl_xor_sync(0xffffffffu, s1, 2);
    const float inv0 = 1.f / s0, inv1 = 1.f / s1;

    // ---- write K smem [px][64 ch] bf16 hi/lo + accumulate kpsum ----
    {
      const int r0 = 16*w + (l >> 2);
      uint32_t* ph = (uint32_t*)(smc + OFF_KHI);
      uint32_t* pl = (uint32_t*)(smc + OFF_KLO);
      #pragma unroll
      for (int nt = 0; nt < 8; nt++) {
        float f0 = acc1[nt][0] * inv0, f1 = acc1[nt][1] * inv0;
        float f2 = acc1[nt][2] * inv1, f3 = acc1[nt][3] * inv1;
        ksum[2*nt]   += f0 + f2;
        ksum[2*nt+1] += f1 + f3;
        int col = nt*8 + cl2;
        int bi0 = r0       * (KSTR/2) + (col >> 1);
        int bi1 = (r0 + 8) * (KSTR/2) + (col >> 1);
        split_store(ph, pl, bi0, f0, f1);
        split_store(ph, pl, bi1, f2, f3);
      }
    }
    __syncthreads();   // bar2: K(t) visible

    // ---- stage 2: P[c,e] += K[c,px] @ X[e,px]^T over 128 px, bf16x3 ----
    #pragma unroll
    for (int ks = 0; ks < 8; ks++) {
      uint32_t ah[4], al[4];
      uint32_t astep = (uint32_t)(ks * 16 * KSTR) * 2;
      ldsm4t(ah, a2off + astep);
      ldsm4t(al, a2off + astep + 18432u);
      #pragma unroll
      for (int dbi = 0; dbi < 2; dbi++) {
        uint32_t bh[4], bl[4];
        uint32_t bo = (uint32_t)(dbi * 16 * XSTR + ks * 16) * 2;
        ldsm4(bh, b2off + bo);
        ldsm4(bl, b2off + bo + XLOD);
        mma16816(acc2[2*dbi],   ah, bh[0], bh[1]);
        mma16816(acc2[2*dbi],   ah, bl[0], bl[1]);
        mma16816(acc2[2*dbi],   al, bh[0], bh[1]);
        mma16816(acc2[2*dbi+1], ah, bh[2], bh[3]);
        mma16816(acc2[2*dbi+1], ah, bl[2], bl[3]);
        mma16816(acc2[2*dbi+1], al, bh[2], bh[3]);
      }
    }
    __syncthreads();   // bar3: stage2(t) done -> Xsm/K free for next conv
  }

  // ---- flush P ----
  float* pp = g_P + (size_t)b * CH * CH;
  const int c0 = c_base + (l >> 2);
  #pragma unroll
  for (int nt = 0; nt < 4; nt++)
    #pragma unroll
    for (int j = 0; j < 2; j++) {
      int d = d_base + nt*8 + cl2 + j;
      atomicAdd(pp + c0*CH + d,       acc2[nt][j]);
      atomicAdd(pp + (c0+8)*CH + d,   acc2[nt][2+j]);
    }

  // ---- flush kpsum ----
  #pragma unroll
  for (int i = 0; i < 16; i++) {
    float s = ksum[i];
    s += __shfl_xor_sync(0xffffffffu, s, 4);
    s += __shfl_xor_sync(0xffffffffu, s, 8);
    s += __shfl_xor_sync(0xffffffffu, s, 16);
    if (l < 4) {
      int ch = (i >> 1)*8 + cl2 + (i & 1);
      atomicAdd(g_kpsum + b*CH + ch, s);
    }
  }
}

// ============ ctx[b][c][d] = sum_e P[b][c][e] Wv[d][e] + kpsum[b][c] bv[d] ============
__global__ void __launch_bounds__(256) ctx_kernel(
    const float* __restrict__ Wv, const float* __restrict__ bv)
{
  __shared__ float Pt[64*68];   // [e][c]
  __shared__ float Wt[64*68];   // [e][d]
  __shared__ float kp[64], bvs[64];
  const int b = blockIdx.x;
  const int tid = threadIdx.x;
  const float* Pg = g_P + (size_t)b * 4096;

  for (int idx = tid; idx < 4096; idx += 256) {
    int r = idx >> 6, e = idx & 63;
    Pt[e*68 + r] = Pg[idx];
    Wt[e*68 + r] = Wv[idx];
  }
  if (tid < 64) { kp[tid] = g_kpsum[b*64 + tid]; bvs[tid] = bv[tid]; }
  __syncthreads();

  const int c0 = (tid >> 4) * 4;
  const int d0 = (tid & 15) * 4;
  float acc[4][4];
  #pragma unroll
  for (int i = 0; i < 4; i++)
    #pragma unroll
    for (int j = 0; j < 4; j++) acc[i][j] = 0.f;

  #pragma unroll 4
  for (int e = 0; e < 64; e++) {
    float4 pc = *(const float4*)&Pt[e*68 + c0];
    float4 wd = *(const float4*)&Wt[e*68 + d0];
    float p[4] = {pc.x, pc.y, pc.z, pc.w};
    float q[4] = {wd.x, wd.y, wd.z, wd.w};
    #pragma unroll
    for (int i = 0; i < 4; i++)
      #pragma unroll
      for (int j = 0; j < 4; j++) acc[i][j] += p[i] * q[j];
  }

  float* cp = g_context + (size_t)b * 4096;
  #pragma unroll
  for (int i = 0; i < 4; i++)
    #pragma unroll
    for (int j = 0; j < 4; j++)
      cp[(c0+i)*64 + d0+j] = acc[i][j] + kp[c0+i] * bvs[d0+j];
}

// dynw: warp -> (i major, b minor) so a block's 4 warps share the same Wfc slice
__global__ void __launch_bounds__(128) dynw_kernel(
    const float* __restrict__ Wfc, const float* __restrict__ bfc)
{
  int p    = blockIdx.x * 4 + (threadIdx.x >> 5);   // 0..4095
  int lane = threadIdx.x & 31;
  int i = p >> 6;            // fc group (same for all 4 warps of a block)
  int b = p & 63;            // batch
  int plane = b * 64 + i;
  const float* ctx = g_context + (size_t)plane * 64;
  float a0 = 1.f / (1.f + __expf(-ctx[lane]));
  float a1 = 1.f / (1.f + __expf(-ctx[lane + 32]));
  // hoist all Wfc loads (L1-resident across the block's 4 warps)
  float wl[9], wh[9];
  #pragma unroll
  for (int j = 0; j < 9; j++) {
    wl[j] = __ldg(Wfc + (i*9 + j)*64 + lane);
    wh[j] = __ldg(Wfc + (i*9 + j)*64 + lane + 32);
  }
  #pragma unroll
  for (int j = 0; j < 9; j++) {
    float s = a0 * wl[j] + a1 * wh[j];
    #pragma unroll
    for (int o = 16; o > 0; o >>= 1) s += __shfl_xor_sync(0xffffffffu, s, o);
    if (lane == 0) g_dynw[plane*9 + j] = s + __ldg(bfc + i*9 + j);
  }
}

// depthwise 3x3, pad 1 — float4/thread, halo via shfl (no smem padding)
#define TROWS 28
__global__ void __launch_bounds__(128) dwconv_kernel(
    const float* __restrict__ x, float* __restrict__ out)
{
  __shared__ float ts[30 * 112];
  const int plane = blockIdx.x;                 // b*64 + c
  const int rb = blockIdx.y * TROWS;
  const float* xp = x + (size_t)plane * HWPIX;
  const int tid = threadIdx.x;
  const int g  = tid >> 5;        // row group 0..3
  const int c4 = tid & 31;        // float4 column (0..27 valid)

  // fill: rows g, g+4, ... < 30 ; each row 28 float4 coalesced
  for (int r = g; r < 30; r += 4) {
    int gr = rb - 1 + r;
    if (c4 < 28) {
      float4 v = make_float4(0.f, 0.f, 0.f, 0.f);
      if (gr >= 0 && gr < HH) v = __ldg((const float4*)(xp + (size_t)gr * WW) + c4);
      *(float4*)&ts[r * 112 + 4 * c4] = v;
    }
  }

  float w[9];
  const float* wp = g_dynw + (size_t)plane * 9;
  #pragma unroll
  for (int k = 0; k < 9; k++) w[k] = __ldg(wp + k);
  __syncthreads();

  const int cc = (c4 < 28) ? c4 : 27;           // clamp for inactive lanes
  const float* rp = ts + (g * 7) * 112 + 4 * cc;

  float4 F0 = *(const float4*)rp;
  float4 F1 = *(const float4*)(rp + 112);
  float L0 = __shfl_up_sync(0xffffffffu, F0.w, 1);   if (c4 == 0)  L0 = 0.f;
  float R0 = __shfl_down_sync(0xffffffffu, F0.x, 1); if (c4 >= 27) R0 = 0.f;
  float L1 = __shfl_up_sync(0xffffffffu, F1.w, 1);   if (c4 == 0)  L1 = 0.f;
  float R1 = __shfl_down_sync(0xffffffffu, F1.x, 1); if (c4 >= 27) R1 = 0.f;

  float* op = out + (size_t)plane * HWPIX + (size_t)(rb + g*7) * WW + 4*c4;
  #pragma unroll
  for (int j = 0; j < 7; j++) {
    float4 F2 = *(const float4*)(rp + (j + 2) * 112);
    float L2 = __shfl_up_sync(0xffffffffu, F2.w, 1);   if (c4 == 0)  L2 = 0.f;
    float R2 = __shfl_down_sync(0xffffffffu, F2.x, 1); if (c4 >= 27) R2 = 0.f;
    float4 o;
    o.x = w[0]*L0   + w[1]*F0.x + w[2]*F0.y
        + w[3]*L1   + w[4]*F1.x + w[5]*F1.y
        + w[6]*L2   + w[7]*F2.x + w[8]*F2.y;
    o.y = w[0]*F0.x + w[1]*F0.y + w[2]*F0.z
        + w[3]*F1.x + w[4]*F1.y + w[5]*F1.z
        + w[6]*F2.x + w[7]*F2.y + w[8]*F2.z;
    o.z = w[0]*F0.y + w[1]*F0.z + w[2]*F0.w
        + w[3]*F1.y + w[4]*F1.z + w[5]*F1.w
        + w[6]*F2.y + w[7]*F2.z + w[8]*F2.w;
    o.w = w[0]*F0.z + w[1]*F0.w + w[2]*R0
        + w[3]*F1.z + w[4]*F1.w + w[5]*R1
        + w[6]*F2.z + w[7]*F2.w + w[8]*R2;
    if (c4 < 28) *(float4*)op = o;
    op += WW;
    L0 = L1; F0 = F1; R0 = R1;
    L1 = L2; F1 = F2; R1 = R2;
  }
}

extern "C" void kernel_launch(void* const* d_in, const int* in_sizes, int n_in,
                              void* d_out, int out_size)
{
  const float* x    = (const float*)d_in[0];
  const float* Wv   = (const float*)d_in[1];
  const float* bv   = (const float*)d_in[2];
  const float* Wm   = (const float*)d_in[3];
  const float* bm   = (const float*)d_in[4];
  const float* gma  = (const float*)d_in[5];
  const float* bta  = (const float*)d_in[6];
  const float* mu   = (const float*)d_in[7];
  const float* var  = (const float*)d_in[8];
  const float* Wfc  = (const float*)d_in[9];
  const float* bfc  = (const float*)d_in[10];
  float* out = (float*)d_out;

  cudaFuncSetAttribute(attn_p_mma,
                       cudaFuncAttributeMaxDynamicSharedMemorySize, SMEMB);

  zero_kernel<<<256, 256>>>();
  attn_p_mma<<<dim3(BLKX, BATCH), 256, SMEMB>>>(x, Wm, bm, gma, bta, mu, var);
  ctx_kernel<<<BATCH, 256>>>(Wv, bv);
  dynw_kernel<<<1024, 128>>>(Wfc, bfc);
  dwconv_kernel<<<dim3(BATCH * CH, HH / TROWS), 128>>>(x, out);
}

// round 14
// speedup vs baseline: 1.4235x; 1.0819x over previous
#include <cuda_runtime.h>
#include <cuda_fp16.h>
#include <cstdint>

#define BATCH 64
#define CH 64
#define HH 112
#define WW 112
#define HWPIX (HH*WW)          // 12544
#define NP 128                 // pixels per tile
#define TPB 7
#define BLKX 14                // 14*7*128 = 12544
#define EPSV 1e-5f

// device scratch (no cudaMalloc allowed)
__device__ float g_P[BATCH*CH*CH];         // [b][c][e] = sum_p k_c(p) x_e(p)
__device__ float g_kpsum[BATCH*CH];        // [b][c]    = sum_p k_c(p)
__device__ float g_context[BATCH*CH*CH];   // [b][c][d]
__device__ float g_dynw[BATCH*CH*9];       // [b*c][9]

// ---------------- smem layout (bytes) ----------------
// X : [64 ch][136 stride] fp16 (hi,lo), SINGLE buffer (stage-1 A + stage-2 B)
// W : [64 out][72 stride] fp16 (hi,lo)  (Wm * bnscale)
// K : [128 px][72 stride] fp16, SINGLE plane (softmaxed key)
#define XSTR  136
#define WSTR  72
#define KSTR  72
#define OFF_XHI  0             // lo at +17408
#define XLOD     17408
#define OFF_WHI  34816         // 9216 bytes
#define OFF_WLO  44032
#define OFF_KHI  53248         // 18432 bytes (single plane)
#define OFF_KSH  71680         // 64 floats BN shift
#define SMEMB    71936

// ---------------- helpers ----------------
__device__ __forceinline__ uint32_t smem_u32(const void* p){
  uint32_t a;
  asm("{ .reg .u64 t; cvta.to.shared.u64 t, %1; cvt.u32.u64 %0, t; }" : "=r"(a) : "l"(p));
  return a;
}
__device__ __forceinline__ void ldsm4(uint32_t* r, uint32_t addr){
  asm volatile("ldmatrix.sync.aligned.m8n8.x4.shared.b16 {%0,%1,%2,%3}, [%4];"
    : "=r"(r[0]), "=r"(r[1]), "=r"(r[2]), "=r"(r[3]) : "r"(addr));
}
__device__ __forceinline__ void ldsm4t(uint32_t* r, uint32_t addr){
  asm volatile("ldmatrix.sync.aligned.m8n8.x4.trans.shared.b16 {%0,%1,%2,%3}, [%4];"
    : "=r"(r[0]), "=r"(r[1]), "=r"(r[2]), "=r"(r[3]) : "r"(addr));
}
__device__ __forceinline__ void mma16816(float* d, const uint32_t* a, uint32_t b0, uint32_t b1){
  asm volatile("mma.sync.aligned.m16n8k16.row.col.f32.f16.f16.f32 "
    "{%0,%1,%2,%3}, {%4,%5,%6,%7}, {%8,%9}, {%0,%1,%2,%3};"
    : "+f"(d[0]), "+f"(d[1]), "+f"(d[2]), "+f"(d[3])
    : "r"(a[0]), "r"(a[1]), "r"(a[2]), "r"(a[3]), "r"(b0), "r"(b1));
}
__device__ __forceinline__ uint32_t packh2(float a, float b){
  __half2 h = __floats2half2_rn(a, b);
  return *(uint32_t*)&h;
}
// fp16 split: hi = rn_f16(f), lo = rn_f16(f - hi); 4 elems -> STS.64 to each plane
__device__ __forceinline__ void split_store2h(uint32_t* ph, uint32_t* pl, int bi,
                                              float f0, float f1, float f2, float f3){
  __half2 h01 = __floats2half2_rn(f0, f1);
  __half2 h23 = __floats2half2_rn(f2, f3);
  uint2 hh; hh.x = *(uint32_t*)&h01; hh.y = *(uint32_t*)&h23;
  *(uint2*)(ph + bi) = hh;
  float2 g01 = __half22float2(h01);
  float2 g23 = __half22float2(h23);
  __half2 l01 = __floats2half2_rn(f0 - g01.x, f1 - g01.y);
  __half2 l23 = __floats2half2_rn(f2 - g23.x, f3 - g23.y);
  uint2 ll; ll.x = *(uint32_t*)&l01; ll.y = *(uint32_t*)&l23;
  *(uint2*)(pl + bi) = ll;
}

__global__ void __launch_bounds__(256) zero_kernel(){
  int i = blockIdx.x * blockDim.x + threadIdx.x;   // 65536 float4
  ((float4*)g_P)[i] = make_float4(0.f,0.f,0.f,0.f);
  if (i < 1024) ((float4*)g_kpsum)[i] = make_float4(0.f,0.f,0.f,0.f);
}

// ============ fused K-attention: P = softmax(BN(Wm X)) @ X^T, fp16 HMMA ============
__global__ void __launch_bounds__(256, 2) attn_p_mma(
    const float* __restrict__ x,
    const float* __restrict__ Wm, const float* __restrict__ bm,
    const float* __restrict__ gma, const float* __restrict__ bta,
    const float* __restrict__ mu,  const float* __restrict__ var)
{
  extern __shared__ char smc[];
  const uint32_t sb = smem_u32(smc);
  const int tid = threadIdx.x;
  const int w   = tid >> 5;        // warp 0..7
  const int l   = tid & 31;
  const int b   = blockIdx.y;

  const int lk = (l & 7) + 8 * (l >> 4);     // ldmatrix row term
  const int lc = 8 * ((l >> 3) & 1);         // ldmatrix col term
  const int cl2 = 2 * (l & 3);

  const float* xb = x + (size_t)b * CH * HWPIX;

  // ---- prefetch X tile 0 into registers ----
  float4 xr[8];
  {
    const int n0 = blockIdx.x * TPB * NP;
    #pragma unroll
    for (int i = 0; i < 8; i++) {
      int f4 = tid + 256 * i;
      int chn = f4 >> 5, pxf = f4 & 31;
      xr[i] = __ldg((const float4*)(xb + (size_t)chn * HWPIX + n0) + pxf);
    }
  }

  // ---- load W = Wm * bnscale (64 rows), fp16 hi/lo, once ----
  {
    uint32_t* ph = (uint32_t*)(smc + OFF_WHI);
    uint32_t* pl = (uint32_t*)(smc + OFF_WLO);
    #pragma unroll
    for (int i = 0; i < 4; i++) {
      int f4 = tid + 256 * i;        // 1024 float4
      int o  = f4 >> 4;
      int c4 = (f4 & 15) * 4;
      float4 v = __ldg((const float4*)(Wm + o*64 + c4));
      float s = __ldg(gma + o) * rsqrtf(__ldg(var + o) + EPSV);
      v.x *= s; v.y *= s; v.z *= s; v.w *= s;
      int bi = o * (WSTR/2) + (c4 >> 1);
      split_store2h(ph, pl, bi, v.x, v.y, v.z, v.w);
    }
  }
  // BN shift (folded) into smem
  if (tid < CH) {
    float sc = __ldg(gma + tid) * rsqrtf(__ldg(var + tid) + EPSV);
    *(float*)(smc + OFF_KSH + tid*4) =
        (__ldg(bm + tid) - __ldg(mu + tid)) * sc + __ldg(bta + tid);
  }

  // ---- persistent accumulators: P tile 16x32 per warp + kpsum partials ----
  const int c_base = (w >> 1) * 16;
  const int d_base = (w & 1) * 32;
  float acc2[4][4];
  #pragma unroll
  for (int i = 0; i < 4; i++)
    #pragma unroll
    for (int j = 0; j < 4; j++) acc2[i][j] = 0.f;
  float ksum[16];
  #pragma unroll
  for (int i = 0; i < 16; i++) ksum[i] = 0.f;

  // ldmatrix base byte offsets (X single buffer, K single plane)
  const uint32_t a1off = sb + OFF_XHI + (uint32_t)(lk*XSTR + 16*w + lc) * 2;
  const uint32_t b1off = sb + OFF_WHI + (uint32_t)(lk*WSTR + lc) * 2;
  const uint32_t a2off = sb + OFF_KHI + (uint32_t)(lk*KSTR + c_base + lc) * 2;
  const uint32_t b2off = sb + OFF_XHI + (uint32_t)((d_base + lk)*XSTR + lc) * 2;

  #pragma unroll 1
  for (int t = 0; t < TPB; t++) {
    // ---- conv X(t) from regs into Xsm (stage2(t-1) finished at bar3) ----
    {
      uint32_t* ph = (uint32_t*)(smc + OFF_XHI);
      uint32_t* pl = (uint32_t*)(smc + OFF_XHI + XLOD);
      #pragma unroll
      for (int i = 0; i < 8; i++) {
        int f4  = tid + 256 * i;
        int chn = f4 >> 5, pxf = f4 & 31;
        int bi = chn * (XSTR/2) + pxf * 2;
        split_store2h(ph, pl, bi, xr[i].x, xr[i].y, xr[i].z, xr[i].w);
      }
    }
    __syncthreads();   // bar1: Xsm(t) (+W on t=0) visible

    // ---- prefetch X(t+1) (hidden behind stage-1 MMAs) ----
    if (t + 1 < TPB) {
      const int n1 = (blockIdx.x * TPB + t + 1) * NP;
      #pragma unroll
      for (int i = 0; i < 8; i++) {
        int f4 = tid + 256 * i;
        int chn = f4 >> 5, pxf = f4 & 31;
        xr[i] = __ldg((const float4*)(xb + (size_t)chn * HWPIX + n1) + pxf);
      }
    }

    // ---- stage 1: logits[16 px of warp][64 ch] = X @ W^T, fp16x3 ----
    float acc1[8][4];
    #pragma unroll
    for (int i = 0; i < 8; i++)
      #pragma unroll
      for (int j = 0; j < 4; j++) acc1[i][j] = 0.f;

    #pragma unroll
    for (int ks = 0; ks < 4; ks++) {
      uint32_t ah[4], al[4];
      uint32_t astep = (uint32_t)(ks * 16 * XSTR) * 2;
      ldsm4t(ah, a1off + astep);
      ldsm4t(al, a1off + astep + XLOD);
      #pragma unroll
      for (int nb = 0; nb < 4; nb++) {
        uint32_t bh[4], bl[4];
        uint32_t bo = (uint32_t)((nb*16) * WSTR + ks*16) * 2;
        ldsm4(bh, b1off + bo);
        ldsm4(bl, b1off + bo + 9216u);
        mma16816(acc1[2*nb],   ah, bh[0], bh[1]);
        mma16816(acc1[2*nb],   ah, bl[0], bl[1]);
        mma16816(acc1[2*nb],   al, bh[0], bh[1]);
        mma16816(acc1[2*nb+1], ah, bh[2], bh[3]);
        mma16816(acc1[2*nb+1], ah, bl[2], bl[3]);
        mma16816(acc1[2*nb+1], al, bh[2], bh[3]);
      }
    }

    // ---- softmax over 64 channels (no max subtraction: logits bounded) ----
    const float* ksm = (const float*)(smc + OFF_KSH);
    float s0 = 0.f, s1 = 0.f;
    #pragma unroll
    for (int nt = 0; nt < 8; nt++)
      #pragma unroll
      for (int j = 0; j < 2; j++) {
        float sh = ksm[nt*8 + cl2 + j];
        acc1[nt][j]   = __expf(acc1[nt][j]   + sh); s0 += acc1[nt][j];
        acc1[nt][2+j] = __expf(acc1[nt][2+j] + sh); s1 += acc1[nt][2+j];
      }
    s0 += __shfl_xor_sync(0xffffffffu, s0, 1);
    s0 += __shfl_xor_sync(0xffffffffu, s0, 2);
    s1 += __shfl_xor_sync(0xffffffffu, s1, 1);
    s1 += __shfl_xor_sync(0xffffffffu, s1, 2);
    const float inv0 = 1.f / s0, inv1 = 1.f / s1;

    // ---- write K smem [px][64 ch] single fp16 plane + accumulate kpsum ----
    {
      const int r0 = 16*w + (l >> 2);
      uint32_t* ph = (uint32_t*)(smc + OFF_KHI);
      #pragma unroll
      for (int nt = 0; nt < 8; nt++) {
        float f0 = acc1[nt][0] * inv0, f1 = acc1[nt][1] * inv0;
        float f2 = acc1[nt][2] * inv1, f3 = acc1[nt][3] * inv1;
        ksum[2*nt]   += f0 + f2;
        ksum[2*nt+1] += f1 + f3;
        int col = nt*8 + cl2;
        ph[r0       * (KSTR/2) + (col >> 1)] = packh2(f0, f1);
        ph[(r0 + 8) * (KSTR/2) + (col >> 1)] = packh2(f2, f3);
      }
    }
    __syncthreads();   // bar2: K(t) visible

    // ---- stage 2: P[c,e] += K[c,px] @ X[e,px]^T over 128 px, fp16x2 ----
    #pragma unroll
    for (int ks = 0; ks < 8; ks++) {
      uint32_t ah[4];
      ldsm4t(ah, a2off + (uint32_t)(ks * 16 * KSTR) * 2);
      #pragma unroll
      for (int dbi = 0; dbi < 2; dbi++) {
        uint32_t bh[4], bl[4];
        uint32_t bo = (uint32_t)(dbi * 16 * XSTR + ks * 16) * 2;
        ldsm4(bh, b2off + bo);
        ldsm4(bl, b2off + bo + XLOD);
        mma16816(acc2[2*dbi],   ah, bh[0], bh[1]);
        mma16816(acc2[2*dbi],   ah, bl[0], bl[1]);
        mma16816(acc2[2*dbi+1], ah, bh[2], bh[3]);
        mma16816(acc2[2*dbi+1], ah, bl[2], bl[3]);
      }
    }
    __syncthreads();   // bar3: stage2(t) done -> Xsm/K free for next conv
  }

  // ---- flush P ----
  float* pp = g_P + (size_t)b * CH * CH;
  const int c0 = c_base + (l >> 2);
  #pragma unroll
  for (int nt = 0; nt < 4; nt++)
    #pragma unroll
    for (int j = 0; j < 2; j++) {
      int d = d_base + nt*8 + cl2 + j;
      atomicAdd(pp + c0*CH + d,       acc2[nt][j]);
      atomicAdd(pp + (c0+8)*CH + d,   acc2[nt][2+j]);
    }

  // ---- flush kpsum ----
  #pragma unroll
  for (int i = 0; i < 16; i++) {
    float s = ksum[i];
    s += __shfl_xor_sync(0xffffffffu, s, 4);
    s += __shfl_xor_sync(0xffffffffu, s, 8);
    s += __shfl_xor_sync(0xffffffffu, s, 16);
    if (l < 4) {
      int ch = (i >> 1)*8 + cl2 + (i & 1);
      atomicAdd(g_kpsum + b*CH + ch, s);
    }
  }
}

// ============ ctx[b][c][d] = sum_e P[b][c][e] Wv[d][e] + kpsum[b][c] bv[d] ============
// 2 blocks per batch (c halves) -> 128 blocks
__global__ void __launch_bounds__(256) ctx_kernel(
    const float* __restrict__ Wv, const float* __restrict__ bv)
{
  __shared__ float Pt[64*34];   // [e][c-half], stride 34
  __shared__ float Wt[64*68];   // [e][d]
  __shared__ float kp[32], bvs[64];
  const int b    = blockIdx.x >> 1;
  const int half = blockIdx.x & 1;
  const int tid  = threadIdx.x;
  const float* Pg = g_P + (size_t)b * 4096 + half * 32 * 64;

  for (int idx = tid; idx < 2048; idx += 256) {   // 32 c x 64 e
    int c = idx >> 6, e = idx & 63;
    Pt[e*34 + c] = Pg[idx];
  }
  for (int idx = tid; idx < 4096; idx += 256) {   // 64 d x 64 e
    int d = idx >> 6, e = idx & 63;
    Wt[e*68 + d] = Wv[idx];
  }
  if (tid < 32) kp[tid]  = g_kpsum[b*64 + half*32 + tid];
  else if (tid < 96) bvs[tid-32] = bv[tid-32];
  __syncthreads();

  const int c0 = (tid >> 4) * 2;       // 2 c per thread (local)
  const int d0 = (tid & 15) * 4;       // 4 d per thread
  float acc[2][4];
  #pragma unroll
  for (int i = 0; i < 2; i++)
    #pragma unroll
    for (int j = 0; j < 4; j++) acc[i][j] = 0.f;

  #pragma unroll 4
  for (int e = 0; e < 64; e++) {
    float2 pc = *(const float2*)&Pt[e*34 + c0];
    float4 wd = *(const float4*)&Wt[e*68 + d0];
    acc[0][0] += pc.x * wd.x; acc[0][1] += pc.x * wd.y;
    acc[0][2] += pc.x * wd.z; acc[0][3] += pc.x * wd.w;
    acc[1][0] += pc.y * wd.x; acc[1][1] += pc.y * wd.y;
    acc[1][2] += pc.y * wd.z; acc[1][3] += pc.y * wd.w;
  }

  float* cp = g_context + (size_t)b * 4096 + (half * 32 + c0) * 64;
  #pragma unroll
  for (int i = 0; i < 2; i++)
    #pragma unroll
    for (int j = 0; j < 4; j++)
      cp[i*64 + d0 + j] = acc[i][j] + kp[c0 + i] * bvs[d0 + j];
}

// dynw: warp -> (i major, b minor) so a block's 4 warps share the same Wfc slice
__global__ void __launch_bounds__(128) dynw_kernel(
    const float* __restrict__ Wfc, const float* __restrict__ bfc)
{
  int p    = blockIdx.x * 4 + (threadIdx.x >> 5);   // 0..4095
  int lane = threadIdx.x & 31;
  int i = p >> 6;            // fc group (same for all 4 warps of a block)
  int b = p & 63;            // batch
  int plane = b * 64 + i;
  const float* ctx = g_context + (size_t)plane * 64;
  float a0 = 1.f / (1.f + __expf(-ctx[lane]));
  float a1 = 1.f / (1.f + __expf(-ctx[lane + 32]));
  float wl[9], wh[9];
  #pragma unroll
  for (int j = 0; j < 9; j++) {
    wl[j] = __ldg(Wfc + (i*9 + j)*64 + lane);
    wh[j] = __ldg(Wfc + (i*9 + j)*64 + lane + 32);
  }
  #pragma unroll
  for (int j = 0; j < 9; j++) {
    float s = a0 * wl[j] + a1 * wh[j];
    #pragma unroll
    for (int o = 16; o > 0; o >>= 1) s += __shfl_xor_sync(0xffffffffu, s, o);
    if (lane == 0) g_dynw[plane*9 + j] = s + __ldg(bfc + i*9 + j);
  }
}

// depthwise 3x3, pad 1 — float4/thread, halo via shfl (no smem padding)
#define TROWS 28
__global__ void __launch_bounds__(128) dwconv_kernel(
    const float* __restrict__ x, float* __restrict__ out)
{
  __shared__ float ts[30 * 112];
  const int plane = blockIdx.x;                 // b*64 + c
  const int rb = blockIdx.y * TROWS;
  const float* xp = x + (size_t)plane * HWPIX;
  const int tid = threadIdx.x;
  const int g  = tid >> 5;        // row group 0..3
  const int c4 = tid & 31;        // float4 column (0..27 valid)

  for (int r = g; r < 30; r += 4) {
    int gr = rb - 1 + r;
    if (c4 < 28) {
      float4 v = make_float4(0.f, 0.f, 0.f, 0.f);
      if (gr >= 0 && gr < HH) v = __ldg((const float4*)(xp + (size_t)gr * WW) + c4);
      *(float4*)&ts[r * 112 + 4 * c4] = v;
    }
  }

  float w[9];
  const float* wp = g_dynw + (size_t)plane * 9;
  #pragma unroll
  for (int k = 0; k < 9; k++) w[k] = __ldg(wp + k);
  __syncthreads();

  const int cc = (c4 < 28) ? c4 : 27;           // clamp for inactive lanes
  const float* rp = ts + (g * 7) * 112 + 4 * cc;

  float4 F0 = *(const float4*)rp;
  float4 F1 = *(const float4*)(rp + 112);
  float L0 = __shfl_up_sync(0xffffffffu, F0.w, 1);   if (c4 == 0)  L0 = 0.f;
  float R0 = __shfl_down_sync(0xffffffffu, F0.x, 1); if (c4 >= 27) R0 = 0.f;
  float L1 = __shfl_up_sync(0xffffffffu, F1.w, 1);   if (c4 == 0)  L1 = 0.f;
  float R1 = __shfl_down_sync(0xffffffffu, F1.x, 1); if (c4 >= 27) R1 = 0.f;

  float* op = out + (size_t)plane * HWPIX + (size_t)(rb + g*7) * WW + 4*c4;
  #pragma unroll
  for (int j = 0; j < 7; j++) {
    float4 F2 = *(const float4*)(rp + (j + 2) * 112);
    float L2 = __shfl_up_sync(0xffffffffu, F2.w, 1);   if (c4 == 0)  L2 = 0.f;
    float R2 = __shfl_down_sync(0xffffffffu, F2.x, 1); if (c4 >= 27) R2 = 0.f;
    float4 o;
    o.x = w[0]*L0   + w[1]*F0.x + w[2]*F0.y
        + w[3]*L1   + w[4]*F1.x + w[5]*F1.y
        + w[6]*L2   + w[7]*F2.x + w[8]*F2.y;
    o.y = w[0]*F0.x + w[1]*F0.y + w[2]*F0.z
        + w[3]*F1.x + w[4]*F1.y + w[5]*F1.z
        + w[6]*F2.x + w[7]*F2.y + w[8]*F2.z;
    o.z = w[0]*F0.y + w[1]*F0.z + w[2]*F0.w
        + w[3]*F1.y + w[4]*F1.z + w[5]*F1.w
        + w[6]*F2.y + w[7]*F2.z + w[8]*F2.w;
    o.w = w[0]*F0.z + w[1]*F0.w + w[2]*R0
        + w[3]*F1.z + w[4]*F1.w + w[5]*R1
        + w[6]*F2.z + w[7]*F2.w + w[8]*R2;
    if (c4 < 28) *(float4*)op = o;
    op += WW;
    L0 = L1; F0 = F1; R0 = R1;
    L1 = L2; F1 = F2; R1 = R2;
  }
}

extern "C" void kernel_launch(void* const* d_in, const int* in_sizes, int n_in,
                              void* d_out, int out_size)
{
  const float* x    = (const float*)d_in[0];
  const float* Wv   = (const float*)d_in[1];
  const float* bv   = (const float*)d_in[2];
  const float* Wm   = (const float*)d_in[3];
  const float* bm   = (const float*)d_in[4];
  const float* gma  = (const float*)d_in[5];
  const float* bta  = (const float*)d_in[6];
  const float* mu   = (const float*)d_in[7];
  const float* var  = (const float*)d_in[8];
  const float* Wfc  = (const float*)d_in[9];
  const float* bfc  = (const float*)d_in[10];
  float* out = (float*)d_out;

  cudaFuncSetAttribute(attn_p_mma,
                       cudaFuncAttributeMaxDynamicSharedMemorySize, SMEMB);

  zero_kernel<<<256, 256>>>();
  attn_p_mma<<<dim3(BLKX, BATCH), 256, SMEMB>>>(x, Wm, bm, gma, bta, mu, var);
  ctx_kernel<<<BATCH * 2, 256>>>(Wv, bv);
  dynw_kernel<<<1024, 128>>>(Wfc, bfc);
  dwconv_kernel<<<dim3(BATCH * CH, HH / TROWS), 128>>>(x, out);
}

// round 15
// speedup vs baseline: 1.5307x; 1.0753x over previous
#include <cuda_runtime.h>
#include <cuda_fp16.h>
#include <cstdint>

#define BATCH 64
#define CH 64
#define HH 112
#define WW 112
#define HWPIX (HH*WW)          // 12544
#define NP 128                 // pixels per tile
#define TPB 7
#define BLKX 14                // 14*7*128 = 12544
#define EPSV 1e-5f

// device scratch (no cudaMalloc allowed)
__device__ float g_P[BATCH*CH*CH];         // [b][c][e] = sum_p k_c(p) x_e(p)
__device__ float g_kpsum[BATCH*CH];        // [b][c]    = sum_p k_c(p)
__device__ float g_context[BATCH*CH*CH];   // [b][c][d]
__device__ float g_dynw[BATCH*CH*9];       // [b*c][9]

// ---------------- smem layout (bytes) ----------------
// X : [64 ch][136 stride] fp16 (hi,lo), SINGLE buffer (stage-1 A + stage-2 B)
// W : [64 out][72 stride] fp16, SINGLE plane (Wm * bnscale)
// K : [128 px][72 stride] fp16, SINGLE plane (softmaxed key)
#define XSTR  136
#define WSTR  72
#define KSTR  72
#define OFF_XHI  0             // lo at +17408
#define XLOD     17408
#define OFF_WHI  34816         // 9216 bytes (single plane)
#define OFF_KHI  44032         // 18432 bytes (single plane)
#define OFF_KSH  62464         // 64 floats BN shift
#define SMEMB    62720

// ---------------- helpers ----------------
__device__ __forceinline__ uint32_t smem_u32(const void* p){
  uint32_t a;
  asm("{ .reg .u64 t; cvta.to.shared.u64 t, %1; cvt.u32.u64 %0, t; }" : "=r"(a) : "l"(p));
  return a;
}
__device__ __forceinline__ void ldsm4(uint32_t* r, uint32_t addr){
  asm volatile("ldmatrix.sync.aligned.m8n8.x4.shared.b16 {%0,%1,%2,%3}, [%4];"
    : "=r"(r[0]), "=r"(r[1]), "=r"(r[2]), "=r"(r[3]) : "r"(addr));
}
__device__ __forceinline__ void ldsm4t(uint32_t* r, uint32_t addr){
  asm volatile("ldmatrix.sync.aligned.m8n8.x4.trans.shared.b16 {%0,%1,%2,%3}, [%4];"
    : "=r"(r[0]), "=r"(r[1]), "=r"(r[2]), "=r"(r[3]) : "r"(addr));
}
__device__ __forceinline__ void mma16816(float* d, const uint32_t* a, uint32_t b0, uint32_t b1){
  asm volatile("mma.sync.aligned.m16n8k16.row.col.f32.f16.f16.f32 "
    "{%0,%1,%2,%3}, {%4,%5,%6,%7}, {%8,%9}, {%0,%1,%2,%3};"
    : "+f"(d[0]), "+f"(d[1]), "+f"(d[2]), "+f"(d[3])
    : "r"(a[0]), "r"(a[1]), "r"(a[2]), "r"(a[3]), "r"(b0), "r"(b1));
}
__device__ __forceinline__ uint32_t packh2(float a, float b){
  __half2 h = __floats2half2_rn(a, b);
  return *(uint32_t*)&h;
}
// fp16 split: hi = rn_f16(f), lo = rn_f16(f - hi); 4 elems -> STS.64 to each plane
__device__ __forceinline__ void split_store2h(uint32_t* ph, uint32_t* pl, int bi,
                                              float f0, float f1, float f2, float f3){
  __half2 h01 = __floats2half2_rn(f0, f1);
  __half2 h23 = __floats2half2_rn(f2, f3);
  uint2 hh; hh.x = *(uint32_t*)&h01; hh.y = *(uint32_t*)&h23;
  *(uint2*)(ph + bi) = hh;
  float2 g01 = __half22float2(h01);
  float2 g23 = __half22float2(h23);
  __half2 l01 = __floats2half2_rn(f0 - g01.x, f1 - g01.y);
  __half2 l23 = __floats2half2_rn(f2 - g23.x, f3 - g23.y);
  uint2 ll; ll.x = *(uint32_t*)&l01; ll.y = *(uint32_t*)&l23;
  *(uint2*)(pl + bi) = ll;
}

__global__ void __launch_bounds__(256) zero_kernel(){
  int i = blockIdx.x * blockDim.x + threadIdx.x;   // 65536 float4
  ((float4*)g_P)[i] = make_float4(0.f,0.f,0.f,0.f);
  if (i < 1024) ((float4*)g_kpsum)[i] = make_float4(0.f,0.f,0.f,0.f);
}

// ============ fused K-attention: P = softmax(BN(Wm X)) @ X^T, fp16 HMMA ============
__global__ void __launch_bounds__(256, 2) attn_p_mma(
    const float* __restrict__ x,
    const float* __restrict__ Wm, const float* __restrict__ bm,
    const float* __restrict__ gma, const float* __restrict__ bta,
    const float* __restrict__ mu,  const float* __restrict__ var)
{
  extern __shared__ char smc[];
  const uint32_t sb = smem_u32(smc);
  const int tid = threadIdx.x;
  const int w   = tid >> 5;        // warp 0..7
  const int l   = tid & 31;
  const int b   = blockIdx.y;

  const int lk = (l & 7) + 8 * (l >> 4);     // ldmatrix row term
  const int lc = 8 * ((l >> 3) & 1);         // ldmatrix col term
  const int cl2 = 2 * (l & 3);

  const float* xb = x + (size_t)b * CH * HWPIX;

  // ---- prefetch X tile 0 into registers ----
  float4 xr[8];
  {
    const int n0 = blockIdx.x * TPB * NP;
    #pragma unroll
    for (int i = 0; i < 8; i++) {
      int f4 = tid + 256 * i;
      int chn = f4 >> 5, pxf = f4 & 31;
      xr[i] = __ldg((const float4*)(xb + (size_t)chn * HWPIX + n0) + pxf);
    }
  }

  // ---- load W = Wm * bnscale (64 rows), single fp16 plane, once ----
  {
    uint32_t* ph = (uint32_t*)(smc + OFF_WHI);
    #pragma unroll
    for (int i = 0; i < 4; i++) {
      int f4 = tid + 256 * i;        // 1024 float4
      int o  = f4 >> 4;
      int c4 = (f4 & 15) * 4;
      float4 v = __ldg((const float4*)(Wm + o*64 + c4));
      float s = __ldg(gma + o) * rsqrtf(__ldg(var + o) + EPSV);
      uint2 hh;
      hh.x = packh2(v.x * s, v.y * s);
      hh.y = packh2(v.z * s, v.w * s);
      *(uint2*)(ph + o * (WSTR/2) + (c4 >> 1)) = hh;
    }
  }
  // BN shift (folded) into smem
  if (tid < CH) {
    float sc = __ldg(gma + tid) * rsqrtf(__ldg(var + tid) + EPSV);
    *(float*)(smc + OFF_KSH + tid*4) =
        (__ldg(bm + tid) - __ldg(mu + tid)) * sc + __ldg(bta + tid);
  }

  // ---- persistent accumulators: P tile 16x32 per warp + kpsum partials ----
  const int c_base = (w >> 1) * 16;
  const int d_base = (w & 1) * 32;
  float acc2[4][4];
  #pragma unroll
  for (int i = 0; i < 4; i++)
    #pragma unroll
    for (int j = 0; j < 4; j++) acc2[i][j] = 0.f;
  float ksum[16];
  #pragma unroll
  for (int i = 0; i < 16; i++) ksum[i] = 0.f;

  // ldmatrix base byte offsets (X single buffer, W/K single plane)
  const uint32_t a1off = sb + OFF_XHI + (uint32_t)(lk*XSTR + 16*w + lc) * 2;
  const uint32_t b1off = sb + OFF_WHI + (uint32_t)(lk*WSTR + lc) * 2;
  const uint32_t a2off = sb + OFF_KHI + (uint32_t)(lk*KSTR + c_base + lc) * 2;
  const uint32_t b2off = sb + OFF_XHI + (uint32_t)((d_base + lk)*XSTR + lc) * 2;

  #pragma unroll 1
  for (int t = 0; t < TPB; t++) {
    // ---- conv X(t) from regs into Xsm (stage2(t-1) finished at bar3) ----
    {
      uint32_t* ph = (uint32_t*)(smc + OFF_XHI);
      uint32_t* pl = (uint32_t*)(smc + OFF_XHI + XLOD);
      #pragma unroll
      for (int i = 0; i < 8; i++) {
        int f4  = tid + 256 * i;
        int chn = f4 >> 5, pxf = f4 & 31;
        int bi = chn * (XSTR/2) + pxf * 2;
        split_store2h(ph, pl, bi, xr[i].x, xr[i].y, xr[i].z, xr[i].w);
      }
    }
    __syncthreads();   // bar1: Xsm(t) (+W on t=0) visible

    // ---- prefetch X(t+1) (hidden behind stage-1 MMAs) ----
    if (t + 1 < TPB) {
      const int n1 = (blockIdx.x * TPB + t + 1) * NP;
      #pragma unroll
      for (int i = 0; i < 8; i++) {
        int f4 = tid + 256 * i;
        int chn = f4 >> 5, pxf = f4 & 31;
        xr[i] = __ldg((const float4*)(xb + (size_t)chn * HWPIX + n1) + pxf);
      }
    }

    // ---- stage 1: logits[16 px of warp][64 ch] = X @ W^T, fp16x2 (X split) ----
    float acc1[8][4];
    #pragma unroll
    for (int i = 0; i < 8; i++)
      #pragma unroll
      for (int j = 0; j < 4; j++) acc1[i][j] = 0.f;

    #pragma unroll
    for (int ks = 0; ks < 4; ks++) {
      uint32_t ah[4], al[4];
      uint32_t astep = (uint32_t)(ks * 16 * XSTR) * 2;
      ldsm4t(ah, a1off + astep);
      ldsm4t(al, a1off + astep + XLOD);
      #pragma unroll
      for (int nb = 0; nb < 4; nb++) {
        uint32_t bh[4];
        ldsm4(bh, b1off + (uint32_t)((nb*16) * WSTR + ks*16) * 2);
        mma16816(acc1[2*nb],   ah, bh[0], bh[1]);
        mma16816(acc1[2*nb],   al, bh[0], bh[1]);
        mma16816(acc1[2*nb+1], ah, bh[2], bh[3]);
        mma16816(acc1[2*nb+1], al, bh[2], bh[3]);
      }
    }

    // ---- softmax over 64 channels (no max subtraction: logits bounded) ----
    const float* ksm = (const float*)(smc + OFF_KSH);
    float s0 = 0.f, s1 = 0.f;
    #pragma unroll
    for (int nt = 0; nt < 8; nt++)
      #pragma unroll
      for (int j = 0; j < 2; j++) {
        float sh = ksm[nt*8 + cl2 + j];
        acc1[nt][j]   = __expf(acc1[nt][j]   + sh); s0 += acc1[nt][j];
        acc1[nt][2+j] = __expf(acc1[nt][2+j] + sh); s1 += acc1[nt][2+j];
      }
    s0 += __shfl_xor_sync(0xffffffffu, s0, 1);
    s0 += __shfl_xor_sync(0xffffffffu, s0, 2);
    s1 += __shfl_xor_sync(0xffffffffu, s1, 1);
    s1 += __shfl_xor_sync(0xffffffffu, s1, 2);
    const float inv0 = 1.f / s0, inv1 = 1.f / s1;

    // ---- write K smem [px][64 ch] single fp16 plane + accumulate kpsum ----
    {
      const int r0 = 16*w + (l >> 2);
      uint32_t* ph = (uint32_t*)(smc + OFF_KHI);
      #pragma unroll
      for (int nt = 0; nt < 8; nt++) {
        float f0 = acc1[nt][0] * inv0, f1 = acc1[nt][1] * inv0;
        float f2 = acc1[nt][2] * inv1, f3 = acc1[nt][3] * inv1;
        ksum[2*nt]   += f0 + f2;
        ksum[2*nt+1] += f1 + f3;
        int col = nt*8 + cl2;
        ph[r0       * (KSTR/2) + (col >> 1)] = packh2(f0, f1);
        ph[(r0 + 8) * (KSTR/2) + (col >> 1)] = packh2(f2, f3);
      }
    }
    __syncthreads();   // bar2: K(t) visible

    // ---- stage 2: P[c,e] += K[c,px] @ X[e,px]^T over 128 px, fp16x2 ----
    #pragma unroll
    for (int ks = 0; ks < 8; ks++) {
      uint32_t ah[4];
      ldsm4t(ah, a2off + (uint32_t)(ks * 16 * KSTR) * 2);
      #pragma unroll
      for (int dbi = 0; dbi < 2; dbi++) {
        uint32_t bh[4], bl[4];
        uint32_t bo = (uint32_t)(dbi * 16 * XSTR + ks * 16) * 2;
        ldsm4(bh, b2off + bo);
        ldsm4(bl, b2off + bo + XLOD);
        mma16816(acc2[2*dbi],   ah, bh[0], bh[1]);
        mma16816(acc2[2*dbi],   ah, bl[0], bl[1]);
        mma16816(acc2[2*dbi+1], ah, bh[2], bh[3]);
        mma16816(acc2[2*dbi+1], ah, bl[2], bl[3]);
      }
    }
    __syncthreads();   // bar3: stage2(t) done -> Xsm/K free for next conv
  }

  // ---- flush P ----
  float* pp = g_P + (size_t)b * CH * CH;
  const int c0 = c_base + (l >> 2);
  #pragma unroll
  for (int nt = 0; nt < 4; nt++)
    #pragma unroll
    for (int j = 0; j < 2; j++) {
      int d = d_base + nt*8 + cl2 + j;
      atomicAdd(pp + c0*CH + d,       acc2[nt][j]);
      atomicAdd(pp + (c0+8)*CH + d,   acc2[nt][2+j]);
    }

  // ---- flush kpsum ----
  #pragma unroll
  for (int i = 0; i < 16; i++) {
    float s = ksum[i];
    s += __shfl_xor_sync(0xffffffffu, s, 4);
    s += __shfl_xor_sync(0xffffffffu, s, 8);
    s += __shfl_xor_sync(0xffffffffu, s, 16);
    if (l < 4) {
      int ch = (i >> 1)*8 + cl2 + (i & 1);
      atomicAdd(g_kpsum + b*CH + ch, s);
    }
  }
}

// ============ ctx[b][c][d] = sum_e P[b][c][e] Wv[d][e] + kpsum[b][c] bv[d] ============
// 2 blocks per batch (c halves) -> 128 blocks
__global__ void __launch_bounds__(256) ctx_kernel(
    const float* __restrict__ Wv, const float* __restrict__ bv)
{
  __shared__ float Pt[64*34];   // [e][c-half], stride 34
  __shared__ float Wt[64*68];   // [e][d]
  __shared__ float kp[32], bvs[64];
  const int b    = blockIdx.x >> 1;
  const int half = blockIdx.x & 1;
  const int tid  = threadIdx.x;
  const float* Pg = g_P + (size_t)b * 4096 + half * 32 * 64;

  for (int idx = tid; idx < 2048; idx += 256) {   // 32 c x 64 e
    int c = idx >> 6, e = idx & 63;
    Pt[e*34 + c] = Pg[idx];
  }
  for (int idx = tid; idx < 4096; idx += 256) {   // 64 d x 64 e
    int d = idx >> 6, e = idx & 63;
    Wt[e*68 + d] = Wv[idx];
  }
  if (tid < 32) kp[tid]  = g_kpsum[b*64 + half*32 + tid];
  else if (tid < 96) bvs[tid-32] = bv[tid-32];
  __syncthreads();

  const int c0 = (tid >> 4) * 2;       // 2 c per thread (local)
  const int d0 = (tid & 15) * 4;       // 4 d per thread
  float acc[2][4];
  #pragma unroll
  for (int i = 0; i < 2; i++)
    #pragma unroll
    for (int j = 0; j < 4; j++) acc[i][j] = 0.f;

  #pragma unroll 4
  for (int e = 0; e < 64; e++) {
    float2 pc = *(const float2*)&Pt[e*34 + c0];
    float4 wd = *(const float4*)&Wt[e*68 + d0];
    acc[0][0] += pc.x * wd.x; acc[0][1] += pc.x * wd.y;
    acc[0][2] += pc.x * wd.z; acc[0][3] += pc.x * wd.w;
    acc[1][0] += pc.y * wd.x; acc[1][1] += pc.y * wd.y;
    acc[1][2] += pc.y * wd.z; acc[1][3] += pc.y * wd.w;
  }

  float* cp = g_context + (size_t)b * 4096 + (half * 32 + c0) * 64;
  #pragma unroll
  for (int i = 0; i < 2; i++)
    #pragma unroll
    for (int j = 0; j < 4; j++)
      cp[i*64 + d0 + j] = acc[i][j] + kp[c0 + i] * bvs[d0 + j];
}

// dynw: warp -> (i major, b minor) so a block's 4 warps share the same Wfc slice
__global__ void __launch_bounds__(128) dynw_kernel(
    const float* __restrict__ Wfc, const float* __restrict__ bfc)
{
  int p    = blockIdx.x * 4 + (threadIdx.x >> 5);   // 0..4095
  int lane = threadIdx.x & 31;
  int i = p >> 6;            // fc group (same for all 4 warps of a block)
  int b = p & 63;            // batch
  int plane = b * 64 + i;
  const float* ctx = g_context + (size_t)plane * 64;
  float a0 = 1.f / (1.f + __expf(-ctx[lane]));
  float a1 = 1.f / (1.f + __expf(-ctx[lane + 32]));
  float wl[9], wh[9];
  #pragma unroll
  for (int j = 0; j < 9; j++) {
    wl[j] = __ldg(Wfc + (i*9 + j)*64 + lane);
    wh[j] = __ldg(Wfc + (i*9 + j)*64 + lane + 32);
  }
  #pragma unroll
  for (int j = 0; j < 9; j++) {
    float s = a0 * wl[j] + a1 * wh[j];
    #pragma unroll
    for (int o = 16; o > 0; o >>= 1) s += __shfl_xor_sync(0xffffffffu, s, o);
    if (lane == 0) g_dynw[plane*9 + j] = s + __ldg(bfc + i*9 + j);
  }
}

// depthwise 3x3, pad 1 — float4/thread, halo via shfl (no smem padding)
#define TROWS 28
__global__ void __launch_bounds__(128) dwconv_kernel(
    const float* __restrict__ x, float* __restrict__ out)
{
  __shared__ float ts[30 * 112];
  const int plane = blockIdx.x;                 // b*64 + c
  const int rb = blockIdx.y * TROWS;
  const float* xp = x + (size_t)plane * HWPIX;
  const int tid = threadIdx.x;
  const int g  = tid >> 5;        // row group 0..3
  const int c4 = tid & 31;        // float4 column (0..27 valid)

  for (int r = g; r < 30; r += 4) {
    int gr = rb - 1 + r;
    if (c4 < 28) {
      float4 v = make_float4(0.f, 0.f, 0.f, 0.f);
      if (gr >= 0 && gr < HH) v = __ldg((const float4*)(xp + (size_t)gr * WW) + c4);
      *(float4*)&ts[r * 112 + 4 * c4] = v;
    }
  }

  float w[9];
  const float* wp = g_dynw + (size_t)plane * 9;
  #pragma unroll
  for (int k = 0; k < 9; k++) w[k] = __ldg(wp + k);
  __syncthreads();

  const int cc = (c4 < 28) ? c4 : 27;           // clamp for inactive lanes
  const float* rp = ts + (g * 7) * 112 + 4 * cc;

  float4 F0 = *(const float4*)rp;
  float4 F1 = *(const float4*)(rp + 112);
  float L0 = __shfl_up_sync(0xffffffffu, F0.w, 1);   if (c4 == 0)  L0 = 0.f;
  float R0 = __shfl_down_sync(0xffffffffu, F0.x, 1); if (c4 >= 27) R0 = 0.f;
  float L1 = __shfl_up_sync(0xffffffffu, F1.w, 1);   if (c4 == 0)  L1 = 0.f;
  float R1 = __shfl_down_sync(0xffffffffu, F1.x, 1); if (c4 >= 27) R1 = 0.f;

  float* op = out + (size_t)plane * HWPIX + (size_t)(rb + g*7) * WW + 4*c4;
  #pragma unroll
  for (int j = 0; j < 7; j++) {
    float4 F2 = *(const float4*)(rp + (j + 2) * 112);
    float L2 = __shfl_up_sync(0xffffffffu, F2.w, 1);   if (c4 == 0)  L2 = 0.f;
    float R2 = __shfl_down_sync(0xffffffffu, F2.x, 1); if (c4 >= 27) R2 = 0.f;
    float4 o;
    o.x = w[0]*L0   + w[1]*F0.x + w[2]*F0.y
        + w[3]*L1   + w[4]*F1.x + w[5]*F1.y
        + w[6]*L2   + w[7]*F2.x + w[8]*F2.y;
    o.y = w[0]*F0.x + w[1]*F0.y + w[2]*F0.z
        + w[3]*F1.x + w[4]*F1.y + w[5]*F1.z
        + w[6]*F2.x + w[7]*F2.y + w[8]*F2.z;
    o.z = w[0]*F0.y + w[1]*F0.z + w[2]*F0.w
        + w[3]*F1.y + w[4]*F1.z + w[5]*F1.w
        + w[6]*F2.y + w[7]*F2.z + w[8]*F2.w;
    o.w = w[0]*F0.z + w[1]*F0.w + w[2]*R0
        + w[3]*F1.z + w[4]*F1.w + w[5]*R1
        + w[6]*F2.z + w[7]*F2.w + w[8]*R2;
    if (c4 < 28) *(float4*)op = o;
    op += WW;
    L0 = L1; F0 = F1; R0 = R1;
    L1 = L2; F1 = F2; R1 = R2;
  }
}

extern "C" void kernel_launch(void* const* d_in, const int* in_sizes, int n_in,
                              void* d_out, int out_size)
{
  const float* x    = (const float*)d_in[0];
  const float* Wv   = (const float*)d_in[1];
  const float* bv   = (const float*)d_in[2];
  const float* Wm   = (const float*)d_in[3];
  const float* bm   = (const float*)d_in[4];
  const float* gma  = (const float*)d_in[5];
  const float* bta  = (const float*)d_in[6];
  const float* mu   = (const float*)d_in[7];
  const float* var  = (const float*)d_in[8];
  const float* Wfc  = (const float*)d_in[9];
  const float* bfc  = (const float*)d_in[10];
  float* out = (float*)d_out;

  cudaFuncSetAttribute(attn_p_mma,
                       cudaFuncAttributeMaxDynamicSharedMemorySize, SMEMB);

  zero_kernel<<<256, 256>>>();
  attn_p_mma<<<dim3(BLKX, BATCH), 256, SMEMB>>>(x, Wm, bm, gma, bta, mu, var);
  ctx_kernel<<<BATCH * 2, 256>>>(Wv, bv);
  dynw_kernel<<<1024, 128>>>(Wfc, bfc);
  dwconv_kernel<<<dim3(BATCH * CH, HH / TROWS), 128>>>(x, out);
}

// round 17
// speedup vs baseline: 1.6061x; 1.0492x over previous
#include <cuda_runtime.h>
#include <cuda_fp16.h>
#include <cstdint>

#define BATCH 64
#define CH 64
#define HH 112
#define WW 112
#define HWPIX (HH*WW)          // 12544
#define NP 128                 // pixels per tile
#define TPB 7
#define BLKX 14                // 14*7*128 = 12544
#define EPSV 1e-5f

// device scratch (no cudaMalloc allowed)
__device__ float g_P[BATCH*CH*CH];         // [b][c][e] = sum_p k_c(p) x_e(p)
__device__ float g_kpsum[BATCH*CH];        // [b][c]    = sum_p k_c(p)
__device__ float g_context[BATCH*CH*CH];   // [b][c][d]
__device__ float g_dynw[BATCH*CH*9];       // [b*c][9]

// ---------------- smem layout (bytes) ----------------
// X : [64 ch][136 stride] fp16 (hi,lo), DOUBLE buffered (stage-1 A + stage-2 B)
// W : [64 out][72 stride] fp16, SINGLE plane (Wm * bnscale)
// K : [128 px][72 stride] fp16, SINGLE plane (softmaxed key)
#define XSTR  136
#define WSTR  72
#define KSTR  72
#define OFF_XHI0 0             // lo at +17408
#define OFF_XHI1 34816         // lo at +17408
#define XLOD     17408
#define OFF_WHI  69632         // 9216 bytes (single plane)
#define OFF_KHI  78848         // 18432 bytes (single plane)
#define OFF_KSH  97280         // 64 floats BN shift
#define SMEMB    97536

// ---------------- helpers ----------------
__device__ __forceinline__ uint32_t smem_u32(const void* p){
  uint32_t a;
  asm("{ .reg .u64 t; cvta.to.shared.u64 t, %1; cvt.u32.u64 %0, t; }" : "=r"(a) : "l"(p));
  return a;
}
__device__ __forceinline__ void ldsm4(uint32_t* r, uint32_t addr){
  asm volatile("ldmatrix.sync.aligned.m8n8.x4.shared.b16 {%0,%1,%2,%3}, [%4];"
    : "=r"(r[0]), "=r"(r[1]), "=r"(r[2]), "=r"(r[3]) : "r"(addr));
}
__device__ __forceinline__ void ldsm4t(uint32_t* r, uint32_t addr){
  asm volatile("ldmatrix.sync.aligned.m8n8.x4.trans.shared.b16 {%0,%1,%2,%3}, [%4];"
    : "=r"(r[0]), "=r"(r[1]), "=r"(r[2]), "=r"(r[3]) : "r"(addr));
}
__device__ __forceinline__ void mma16816(float* d, const uint32_t* a, uint32_t b0, uint32_t b1){
  asm volatile("mma.sync.aligned.m16n8k16.row.col.f32.f16.f16.f32 "
    "{%0,%1,%2,%3}, {%4,%5,%6,%7}, {%8,%9}, {%0,%1,%2,%3};"
    : "+f"(d[0]), "+f"(d[1]), "+f"(d[2]), "+f"(d[3])
    : "r"(a[0]), "r"(a[1]), "r"(a[2]), "r"(a[3]), "r"(b0), "r"(b1));
}
__device__ __forceinline__ uint32_t packh2(float a, float b){
  __half2 h = __floats2half2_rn(a, b);
  return *(uint32_t*)&h;
}
// fp16 split: hi = rn_f16(f), lo = rn_f16(f - hi); 4 elems -> STS.64 to each plane
__device__ __forceinline__ void split_store2h(uint32_t* ph, uint32_t* pl, int bi,
                                              float f0, float f1, float f2, float f3){
  __half2 h01 = __floats2half2_rn(f0, f1);
  __half2 h23 = __floats2half2_rn(f2, f3);
  uint2 hh; hh.x = *(uint32_t*)&h01; hh.y = *(uint32_t*)&h23;
  *(uint2*)(ph + bi) = hh;
  float2 g01 = __half22float2(h01);
  float2 g23 = __half22float2(h23);
  __half2 l01 = __floats2half2_rn(f0 - g01.x, f1 - g01.y);
  __half2 l23 = __floats2half2_rn(f2 - g23.x, f3 - g23.y);
  uint2 ll; ll.x = *(uint32_t*)&l01; ll.y = *(uint32_t*)&l23;
  *(uint2*)(pl + bi) = ll;
}

__global__ void __launch_bounds__(256) zero_kernel(){
  int i = blockIdx.x * blockDim.x + threadIdx.x;   // 65536 float4
  ((float4*)g_P)[i] = make_float4(0.f,0.f,0.f,0.f);
  if (i < 1024) ((float4*)g_kpsum)[i] = make_float4(0.f,0.f,0.f,0.f);
}

// ============ fused K-attention: P = softmax(BN(Wm X)) @ X^T, fp16 HMMA ============
__global__ void __launch_bounds__(256, 2) attn_p_mma(
    const float* __restrict__ x,
    const float* __restrict__ Wm, const float* __restrict__ bm,
    const float* __restrict__ gma, const float* __restrict__ bta,
    const float* __restrict__ mu,  const float* __restrict__ var)
{
  extern __shared__ char smc[];
  const uint32_t sb = smem_u32(smc);
  const int tid = threadIdx.x;
  const int w   = tid >> 5;        // warp 0..7
  const int l   = tid & 31;
  const int b   = blockIdx.y;

  const int lk = (l & 7) + 8 * (l >> 4);     // ldmatrix row term
  const int lc = 8 * ((l >> 3) & 1);         // ldmatrix col term
  const int cl2 = 2 * (l & 3);

  const float* xb = x + (size_t)b * CH * HWPIX;

  // ---- prefetch X tile 0 into registers ----
  float4 xr[8];
  {
    const int n0 = blockIdx.x * TPB * NP;
    #pragma unroll
    for (int i = 0; i < 8; i++) {
      int f4 = tid + 256 * i;
      int chn = f4 >> 5, pxf = f4 & 31;
      xr[i] = __ldg((const float4*)(xb + (size_t)chn * HWPIX + n0) + pxf);
    }
  }

  // ---- load W = Wm * bnscale (64 rows), single fp16 plane, once ----
  {
    uint32_t* ph = (uint32_t*)(smc + OFF_WHI);
    #pragma unroll
    for (int i = 0; i < 4; i++) {
      int f4 = tid + 256 * i;        // 1024 float4
      int o  = f4 >> 4;
      int c4 = (f4 & 15) * 4;
      float4 v = __ldg((const float4*)(Wm + o*64 + c4));
      float s = __ldg(gma + o) * rsqrtf(__ldg(var + o) + EPSV);
      uint2 hh;
      hh.x = packh2(v.x * s, v.y * s);
      hh.y = packh2(v.z * s, v.w * s);
      *(uint2*)(ph + o * (WSTR/2) + (c4 >> 1)) = hh;
    }
  }
  // BN shift (folded) into smem
  if (tid < CH) {
    float sc = __ldg(gma + tid) * rsqrtf(__ldg(var + tid) + EPSV);
    *(float*)(smc + OFF_KSH + tid*4) =
        (__ldg(bm + tid) - __ldg(mu + tid)) * sc + __ldg(bta + tid);
  }

  // ---- persistent accumulators: P tile 16x32 per warp + kpsum partials ----
  const int c_base = (w >> 1) * 16;
  const int d_base = (w & 1) * 32;
  float acc2[4][4];
  #pragma unroll
  for (int i = 0; i < 4; i++)
    #pragma unroll
    for (int j = 0; j < 4; j++) acc2[i][j] = 0.f;
  float ksum[16];
  #pragma unroll
  for (int i = 0; i < 16; i++) ksum[i] = 0.f;

  // ldmatrix base byte offsets (X double buffer, W/K single plane)
  const uint32_t a1term = (uint32_t)(lk*XSTR + 16*w + lc) * 2;
  const uint32_t b1off  = sb + OFF_WHI + (uint32_t)(lk*WSTR + lc) * 2;
  const uint32_t a2off  = sb + OFF_KHI + (uint32_t)(lk*KSTR + c_base + lc) * 2;
  const uint32_t b2term = (uint32_t)((d_base + lk)*XSTR + lc) * 2;

  #pragma unroll 1
  for (int t = 0; t < TPB; t++) {
    const uint32_t xbuf = (t & 1) ? OFF_XHI1 : OFF_XHI0;

    // ---- conv X(t) from regs into buffer t&1 (other buffer may still be
    //      read by stage2(t-1) of slower warps — disjoint, no barrier) ----
    {
      uint32_t* ph = (uint32_t*)(smc + xbuf);
      uint32_t* pl = (uint32_t*)(smc + xbuf + XLOD);
      #pragma unroll
      for (int i = 0; i < 8; i++) {
        int f4  = tid + 256 * i;
        int chn = f4 >> 5, pxf = f4 & 31;
        int bi = chn * (XSTR/2) + pxf * 2;
        split_store2h(ph, pl, bi, xr[i].x, xr[i].y, xr[i].z, xr[i].w);
      }
    }
    __syncthreads();   // bar1: Xsm(t) (+W on t=0) visible; all stage2(t-1) done

    // ---- prefetch X(t+1) (hidden behind stage-1 MMAs) ----
    if (t + 1 < TPB) {
      const int n1 = (blockIdx.x * TPB + t + 1) * NP;
      #pragma unroll
      for (int i = 0; i < 8; i++) {
        int f4 = tid + 256 * i;
        int chn = f4 >> 5, pxf = f4 & 31;
        xr[i] = __ldg((const float4*)(xb + (size_t)chn * HWPIX + n1) + pxf);
      }
    }

    // ---- stage 1: logits[16 px of warp][64 ch] = X @ W^T, fp16x2 (X split) ----
    float acc1[8][4];
    #pragma unroll
    for (int i = 0; i < 8; i++)
      #pragma unroll
      for (int j = 0; j < 4; j++) acc1[i][j] = 0.f;

    const uint32_t a1off = sb + xbuf + a1term;
    #pragma unroll
    for (int ks = 0; ks < 4; ks++) {
      uint32_t ah[4], al[4];
      uint32_t astep = (uint32_t)(ks * 16 * XSTR) * 2;
      ldsm4t(ah, a1off + astep);
      ldsm4t(al, a1off + astep + XLOD);
      #pragma unroll
      for (int nb = 0; nb < 4; nb++) {
        uint32_t bh[4];
        ldsm4(bh, b1off + (uint32_t)((nb*16) * WSTR + ks*16) * 2);
        mma16816(acc1[2*nb],   ah, bh[0], bh[1]);
        mma16816(acc1[2*nb],   al, bh[0], bh[1]);
        mma16816(acc1[2*nb+1], ah, bh[2], bh[3]);
        mma16816(acc1[2*nb+1], al, bh[2], bh[3]);
      }
    }

    // ---- softmax over 64 channels (no max subtraction: logits bounded) ----
    const float* ksm = (const float*)(smc + OFF_KSH);
    float s0 = 0.f, s1 = 0.f;
    #pragma unroll
    for (int nt = 0; nt < 8; nt++)
      #pragma unroll
      for (int j = 0; j < 2; j++) {
        float sh = ksm[nt*8 + cl2 + j];
        acc1[nt][j]   = __expf(acc1[nt][j]   + sh); s0 += acc1[nt][j];
        acc1[nt][2+j] = __expf(acc1[nt][2+j] + sh); s1 += acc1[nt][2+j];
      }
    s0 += __shfl_xor_sync(0xffffffffu, s0, 1);
    s0 += __shfl_xor_sync(0xffffffffu, s0, 2);
    s1 += __shfl_xor_sync(0xffffffffu, s1, 1);
    s1 += __shfl_xor_sync(0xffffffffu, s1, 2);
    const float inv0 = 1.f / s0, inv1 = 1.f / s1;

    // ---- write K smem [px][64 ch] single fp16 plane + accumulate kpsum ----
    // (safe vs stage2(t-1): every warp passed bar1 after its stage2(t-1))
    {
      const int r0 = 16*w + (l >> 2);
      uint32_t* ph = (uint32_t*)(smc + OFF_KHI);
      #pragma unroll
      for (int nt = 0; nt < 8; nt++) {
        float f0 = acc1[nt][0] * inv0, f1 = acc1[nt][1] * inv0;
        float f2 = acc1[nt][2] * inv1, f3 = acc1[nt][3] * inv1;
        ksum[2*nt]   += f0 + f2;
        ksum[2*nt+1] += f1 + f3;
        int col = nt*8 + cl2;
        ph[r0       * (KSTR/2) + (col >> 1)] = packh2(f0, f1);
        ph[(r0 + 8) * (KSTR/2) + (col >> 1)] = packh2(f2, f3);
      }
    }
    __syncthreads();   // bar2: K(t) visible

    // ---- stage 2: P[c,e] += K[c,px] @ X[e,px]^T over 128 px, fp16x2 ----
    const uint32_t b2off = sb + xbuf + b2term;
    #pragma unroll
    for (int ks = 0; ks < 8; ks++) {
      uint32_t ah[4];
      ldsm4t(ah, a2off + (uint32_t)(ks * 16 * KSTR) * 2);
      #pragma unroll
      for (int dbi = 0; dbi < 2; dbi++) {
        uint32_t bh[4], bl[4];
        uint32_t bo = (uint32_t)(dbi * 16 * XSTR + ks * 16) * 2;
        ldsm4(bh, b2off + bo);
        ldsm4(bl, b2off + bo + XLOD);
        mma16816(acc2[2*dbi],   ah, bh[0], bh[1]);
        mma16816(acc2[2*dbi],   ah, bl[0], bl[1]);
        mma16816(acc2[2*dbi+1], ah, bh[2], bh[3]);
        mma16816(acc2[2*dbi+1], ah, bl[2], bl[3]);
      }
    }
    // no bar3: X double-buffered, K rewrite guarded by bar1(t+1)
  }

  // ---- flush P ----
  float* pp = g_P + (size_t)b * CH * CH;
  const int c0 = c_base + (l >> 2);
  #pragma unroll
  for (int nt = 0; nt < 4; nt++)
    #pragma unroll
    for (int j = 0; j < 2; j++) {
      int d = d_base + nt*8 + cl2 + j;
      atomicAdd(pp + c0*CH + d,       acc2[nt][j]);
      atomicAdd(pp + (c0+8)*CH + d,   acc2[nt][2+j]);
    }

  // ---- flush kpsum ----
  #pragma unroll
  for (int i = 0; i < 16; i++) {
    float s = ksum[i];
    s += __shfl_xor_sync(0xffffffffu, s, 4);
    s += __shfl_xor_sync(0xffffffffu, s, 8);
    s += __shfl_xor_sync(0xffffffffu, s, 16);
    if (l < 4) {
      int ch = (i >> 1)*8 + cl2 + (i & 1);
      atomicAdd(g_kpsum + b*CH + ch, s);
    }
  }
}

// ============ ctx[b][c][d] = sum_e P[b][c][e] Wv[d][e] + kpsum[b][c] bv[d] ============
// 2 blocks per batch (c halves) -> 128 blocks
__global__ void __launch_bounds__(256) ctx_kernel(
    const float* __restrict__ Wv, const float* __restrict__ bv)
{
  __shared__ float Pt[64*34];   // [e][c-half], stride 34
  __shared__ float Wt[64*68];   // [e][d]
  __shared__ float kp[32], bvs[64];
  const int b    = blockIdx.x >> 1;
  const int half = blockIdx.x & 1;
  const int tid  = threadIdx.x;
  const float* Pg = g_P + (size_t)b * 4096 + half * 32 * 64;

  for (int idx = tid; idx < 2048; idx += 256) {   // 32 c x 64 e
    int c = idx >> 6, e = idx & 63;
    Pt[e*34 + c] = Pg[idx];
  }
  for (int idx = tid; idx < 4096; idx += 256) {   // 64 d x 64 e
    int d = idx >> 6, e = idx & 63;
    Wt[e*68 + d] = Wv[idx];
  }
  if (tid < 32) kp[tid]  = g_kpsum[b*64 + half*32 + tid];
  else if (tid < 96) bvs[tid-32] = bv[tid-32];
  __syncthreads();

  const int c0 = (tid >> 4) * 2;       // 2 c per thread (local)
  const int d0 = (tid & 15) * 4;       // 4 d per thread
  float acc[2][4];
  #pragma unroll
  for (int i = 0; i < 2; i++)
    #pragma unroll
    for (int j = 0; j < 4; j++) acc[i][j] = 0.f;

  #pragma unroll 4
  for (int e = 0; e < 64; e++) {
    float2 pc = *(const float2*)&Pt[e*34 + c0];
    float4 wd = *(const float4*)&Wt[e*68 + d0];
    acc[0][0] += pc.x * wd.x; acc[0][1] += pc.x * wd.y;
    acc[0][2] += pc.x * wd.z; acc[0][3] += pc.x * wd.w;
    acc[1][0] += pc.y * wd.x; acc[1][1] += pc.y * wd.y;
    acc[1][2] += pc.y * wd.z; acc[1][3] += pc.y * wd.w;
  }

  float* cp = g_context + (size_t)b * 4096 + (half * 32 + c0) * 64;
  #pragma unroll
  for (int i = 0; i < 2; i++)
    #pragma unroll
    for (int j = 0; j < 4; j++)
      cp[i*64 + d0 + j] = acc[i][j] + kp[c0 + i] * bvs[d0 + j];
}

// dynw: warp -> (i major, b minor) so a block's 4 warps share the same Wfc slice
__global__ void __launch_bounds__(128) dynw_kernel(
    const float* __restrict__ Wfc, const float* __restrict__ bfc)
{
  int p    = blockIdx.x * 4 + (threadIdx.x >> 5);   // 0..4095
  int lane = threadIdx.x & 31;
  int i = p >> 6;            // fc group (same for all 4 warps of a block)
  int b = p & 63;            // batch
  int plane = b * 64 + i;
  const float* ctx = g_context + (size_t)plane * 64;
  float a0 = 1.f / (1.f + __expf(-ctx[lane]));
  float a1 = 1.f / (1.f + __expf(-ctx[lane + 32]));
  float wl[9], wh[9];
  #pragma unroll
  for (int j = 0; j < 9; j++) {
    wl[j] = __ldg(Wfc + (i*9 + j)*64 + lane);
    wh[j] = __ldg(Wfc + (i*9 + j)*64 + lane + 32);
  }
  #pragma unroll
  for (int j = 0; j < 9; j++) {
    float s = a0 * wl[j] + a1 * wh[j];
    #pragma unroll
    for (int o = 16; o > 0; o >>= 1) s += __shfl_xor_sync(0xffffffffu, s, o);
    if (lane == 0) g_dynw[plane*9 + j] = s + __ldg(bfc + i*9 + j);
  }
}

// depthwise 3x3, pad 1 — NO smem: 9 gmem rows/thread (MLP=9), shfl halos
#define TROWS 28
__global__ void __launch_bounds__(128) dwconv_kernel(
    const float* __restrict__ x, float* __restrict__ out)
{
  const int plane = blockIdx.x;                 // b*64 + c
  const int rb = blockIdx.y * TROWS;
  const int tid = threadIdx.x;
  const int g  = tid >> 5;        // warp = row group 0..3 (7 rows each)
  const int c4 = tid & 31;        // float4 column (0..27 valid)
  const int cc = (c4 < 28) ? c4 : 27;
  const int r0 = rb + g * 7;      // first output row of this warp
  const float* xp = x + (size_t)plane * HWPIX;

  float w[9];
  const float* wp = g_dynw + (size_t)plane * 9;
  #pragma unroll
  for (int k = 0; k < 9; k++) w[k] = __ldg(wp + k);

  // load 9 rows (r0-1 .. r0+7) as float4, all in flight at once
  float4 F[9];
  #pragma unroll
  for (int r = 0; r < 9; r++) {
    int gr = r0 - 1 + r;
    float4 v = make_float4(0.f, 0.f, 0.f, 0.f);
    if (gr >= 0 && gr < HH) v = __ldg((const float4*)(xp + (size_t)gr * WW) + cc);
    F[r] = v;
  }
  // halos via shfl (all lanes participate)
  float L[9], R[9];
  #pragma unroll
  for (int r = 0; r < 9; r++) {
    L[r] = __shfl_up_sync(0xffffffffu, F[r].w, 1);   if (c4 == 0)  L[r] = 0.f;
    R[r] = __shfl_down_sync(0xffffffffu, F[r].x, 1); if (c4 >= 27) R[r] = 0.f;
  }

  if (c4 < 28) {
    float* op = out + (size_t)plane * HWPIX + (size_t)r0 * WW + 4 * c4;
    #pragma unroll
    for (int j = 0; j < 7; j++) {
      float4 o;
      o.x = w[0]*L[j]     + w[1]*F[j].x   + w[2]*F[j].y
          + w[3]*L[j+1]   + w[4]*F[j+1].x + w[5]*F[j+1].y
          + w[6]*L[j+2]   + w[7]*F[j+2].x + w[8]*F[j+2].y;
      o.y = w[0]*F[j].x   + w[1]*F[j].y   + w[2]*F[j].z
          + w[3]*F[j+1].x + w[4]*F[j+1].y + w[5]*F[j+1].z
          + w[6]*F[j+2].x + w[7]*F[j+2].y + w[8]*F[j+2].z;
      o.z = w[0]*F[j].y   + w[1]*F[j].z   + w[2]*F[j].w
          + w[3]*F[j+1].y + w[4]*F[j+1].z + w[5]*F[j+1].w
          + w[6]*F[j+2].y + w[7]*F[j+2].z + w[8]*F[j+2].w;
      o.w = w[0]*F[j].z   + w[1]*F[j].w   + w[2]*R[j]
          + w[3]*F[j+1].z + w[4]*F[j+1].w + w[5]*R[j+1]
          + w[6]*F[j+2].z + w[7]*F[j+2].w + w[8]*R[j+2];
      *(float4*)(op + (size_t)j * WW) = o;
    }
  }
}

extern "C" void kernel_launch(void* const* d_in, const int* in_sizes, int n_in,
                              void* d_out, int out_size)
{
  const float* x    = (const float*)d_in[0];
  const float* Wv   = (const float*)d_in[1];
  const float* bv   = (const float*)d_in[2];
  const float* Wm   = (const float*)d_in[3];
  const float* bm   = (const float*)d_in[4];
  const float* gma  = (const float*)d_in[5];
  const float* bta  = (const float*)d_in[6];
  const float* mu   = (const float*)d_in[7];
  const float* var  = (const float*)d_in[8];
  const float* Wfc  = (const float*)d_in[9];
  const float* bfc  = (const float*)d_in[10];
  float* out = (float*)d_out;

  cudaFuncSetAttribute(attn_p_mma,
                       cudaFuncAttributeMaxDynamicSharedMemorySize, SMEMB);

  zero_kernel<<<256, 256>>>();
  attn_p_mma<<<dim3(BLKX, BATCH), 256, SMEMB>>>(x, Wm, bm, gma, bta, mu, var);
  ctx_kernel<<<BATCH * 2, 256>>>(Wv, bv);
  dynw_kernel<<<1024, 128>>>(Wfc, bfc);
  dwconv_kernel<<<dim3(BATCH * CH, HH / TROWS), 128>>>(x, out);
}